// round 6
// baseline (speedup 1.0000x reference)
#include <cuda_runtime.h>
#include <math.h>
#include <stdint.h>

#define NMAX   50000
#define EMAX   700000     // 650000 edges + 50000 self loops
#define FDIM   256
#define HEADS  4
#define NEG_SLOPE 0.2f

// ---------------- scratch (device globals; no allocation allowed) -----------
__device__ int   g_src [EMAX];
__device__ int   g_dst [EMAX];
__device__ int   g_ssrc[EMAX];
__device__ int   g_deg [NMAX];          // zero at load; re-zeroed by k_scatter
__device__ int   g_incl[NMAX];
__device__ int   g_part[64];
__device__ int   g_off [NMAX + 1];
__device__ int   g_cur [NMAX];
__device__ __align__(16) float g_feat[NMAX * FDIM];
__device__ __align__(16) float g_act [NMAX * FDIM];
__device__ __align__(16) float g_alsrc[NMAX * HEADS];
__device__ __align__(16) float g_aldst[NMAX * HEADS];
__device__ float g_h3  [NMAX];

// ---------------- helpers ---------------------------------------------------
__device__ __forceinline__ float lrelu(float x) { return x > 0.f ? x : NEG_SLOPE * x; }
__device__ __forceinline__ float wsum(float v) {
    #pragma unroll
    for (int o = 16; o; o >>= 1) v += __shfl_xor_sync(0xffffffffu, v, o);
    return v;
}
__device__ __forceinline__ uint32_t f2tf(float f) {
    uint32_t r;
    asm("cvt.rna.tf32.f32 %0, %1;" : "=r"(r) : "f"(f));
    return r;
}
__device__ __forceinline__ void mma_tf32(float* d, const uint32_t* a, const uint32_t* b) {
    asm volatile(
        "mma.sync.aligned.m16n8k8.row.col.f32.tf32.tf32.f32 "
        "{%0,%1,%2,%3}, {%4,%5,%6,%7}, {%8,%9}, {%0,%1,%2,%3};"
        : "+f"(d[0]), "+f"(d[1]), "+f"(d[2]), "+f"(d[3])
        : "r"(a[0]), "r"(a[1]), "r"(a[2]), "r"(a[3]), "r"(b[0]), "r"(b[1]));
}
__device__ __forceinline__ void cp16z(uint32_t s, const void* g, int sz) {
    asm volatile("cp.async.cg.shared.global [%0], [%1], 16, %2;"
                 :: "r"(s), "l"(g), "r"(sz));
}
__device__ __forceinline__ void cp_commit() { asm volatile("cp.async.commit_group;"); }
__device__ __forceinline__ void cp_wait1()  { asm volatile("cp.async.wait_group 1;"); }

// ---------------- graph build (build + histogram fused) ----------------------
__global__ void k_buildhist(const long long* __restrict__ e, int E, int N) {
    int i = blockIdx.x * blockDim.x + threadIdx.x;
    bool is64 = true;
    #pragma unroll
    for (int j = 0; j < 8; j++) {
        unsigned long long v = (unsigned long long)__ldg(&e[j * 7 + 1]);
        if (v >= (1ULL << 31)) is64 = false;
    }
    if (i < E) {
        int s, d;
        if (is64) { s = (int)e[i]; d = (int)e[E + i]; }
        else      { const int* p = (const int*)e; s = p[i]; d = p[E + i]; }
        g_src[i] = s; g_dst[i] = d;
        atomicAdd(&g_deg[d], 1);
    } else if (i < E + N) {
        int n = i - E;
        g_src[i] = n; g_dst[i] = n;
        atomicAdd(&g_deg[n], 1);
    }
}

__global__ void k_scanA(int n) {
    __shared__ int sh[1024];
    int tid = threadIdx.x;
    int i = blockIdx.x * 1024 + tid;
    sh[tid] = (i < n) ? g_deg[i] : 0;
    __syncthreads();
    #pragma unroll
    for (int o = 1; o < 1024; o <<= 1) {
        int t = (tid >= o) ? sh[tid - o] : 0;
        __syncthreads();
        sh[tid] += t;
        __syncthreads();
    }
    if (i < n) g_incl[i] = sh[tid];
    if (tid == 1023) g_part[blockIdx.x] = sh[1023];
}

__global__ void k_scanC(int n) {
    int i = blockIdx.x * blockDim.x + threadIdx.x;
    if (i < n) {
        int chunk = i >> 10;
        int base = 0;
        for (int b = 0; b < chunk; b++) base += g_part[b];
        int incl = g_incl[i] + base;
        g_off[i + 1] = incl;
        g_cur[i] = incl - g_deg[i];
    }
    if (i == 0) g_off[0] = 0;
}

__global__ void k_scatter(int Etot, int N) {
    int i = blockIdx.x * blockDim.x + threadIdx.x;
    if (i < Etot) {
        int p = atomicAdd(&g_cur[g_dst[i]], 1);
        g_ssrc[p] = g_src[i];
    }
    if (i < N) g_deg[i] = 0;     // reset for next graph replay (scan is done)
}

// ---------------- tf32 MMA GEMM with cp.async double buffering ---------------
// C[M,256] = A[M,K] * B[K,256]; BM=128 BN=128 BK=16, 256 threads, warp 32x64
__global__ __launch_bounds__(256) void k_gemm(const float* __restrict__ A,
                                              const float* __restrict__ B,
                                              float* __restrict__ C,
                                              int M, int K) {
    __shared__ float As[2][128][20];   // [m][k] padded to 20 (16B-aligned rows)
    __shared__ float Bs[2][16][136];   // [k][n] padded to 136
    int tid = threadIdx.x;
    int lane = tid & 31, wid = tid >> 5;
    int gid = lane >> 2, tig = lane & 3;
    int warp_m = wid >> 1, warp_n = wid & 1;
    int brow = blockIdx.y * 128, bcol = blockIdx.x * 128;

    // per-thread load assignments (2 x 16B for A, 2 x 16B for B per stage)
    int ar0 = tid >> 2,          ak0 = (tid & 3) << 2;          // chunk tid
    int ar1 = (tid + 256) >> 2,  ak1 = ((tid + 256) & 3) << 2;  // chunk tid+256
    int bk0 = tid >> 5,          bn0 = (tid & 31) << 2;
    int bk1 = (tid + 256) >> 5,  bn1 = ((tid + 256) & 31) << 2;
    bool av0 = (brow + ar0) < M, av1 = (brow + ar1) < M;
    const float* Ar0 = A + (size_t)(av0 ? brow + ar0 : 0) * K + ak0;
    const float* Ar1 = A + (size_t)(av1 ? brow + ar1 : 0) * K + ak1;
    const float* Br0 = B + (size_t)bk0 * FDIM + bcol + bn0;
    const float* Br1 = B + (size_t)bk1 * FDIM + bcol + bn1;

    uint32_t sa0[2], sa1[2], sb0[2], sb1[2];
    #pragma unroll
    for (int s = 0; s < 2; s++) {
        sa0[s] = (uint32_t)__cvta_generic_to_shared(&As[s][ar0][ak0]);
        sa1[s] = (uint32_t)__cvta_generic_to_shared(&As[s][ar1][ak1]);
        sb0[s] = (uint32_t)__cvta_generic_to_shared(&Bs[s][bk0][bn0]);
        sb1[s] = (uint32_t)__cvta_generic_to_shared(&Bs[s][bk1][bn1]);
    }

    float acc[2][8][4];
    #pragma unroll
    for (int mt = 0; mt < 2; mt++)
        #pragma unroll
        for (int nt = 0; nt < 8; nt++)
            #pragma unroll
            for (int q = 0; q < 4; q++) acc[mt][nt][q] = 0.f;

    int ntile = K >> 4;
    // prologue: stage 0
    cp16z(sa0[0], Ar0, av0 ? 16 : 0);
    cp16z(sa1[0], Ar1, av1 ? 16 : 0);
    cp16z(sb0[0], Br0, 16);
    cp16z(sb1[0], Br1, 16);
    cp_commit();

    for (int t = 0; t < ntile; t++) {
        int nxt = t + 1;
        if (nxt < ntile) {                        // issue next tile
            int slot = nxt & 1;
            cp16z(sa0[slot], Ar0 + nxt * 16, av0 ? 16 : 0);
            cp16z(sa1[slot], Ar1 + nxt * 16, av1 ? 16 : 0);
            cp16z(sb0[slot], Br0 + (size_t)nxt * 16 * FDIM, 16);
            cp16z(sb1[slot], Br1 + (size_t)nxt * 16 * FDIM, 16);
        }
        cp_commit();
        cp_wait1();                               // tile t resident
        __syncthreads();
        int cur = t & 1;
        #pragma unroll
        for (int k8 = 0; k8 < 2; k8++) {
            int kb = k8 * 8;
            uint32_t af[2][4];
            #pragma unroll
            for (int mt = 0; mt < 2; mt++) {
                int mb = warp_m * 32 + mt * 16 + gid;
                af[mt][0] = f2tf(As[cur][mb    ][kb + tig]);
                af[mt][1] = f2tf(As[cur][mb + 8][kb + tig]);
                af[mt][2] = f2tf(As[cur][mb    ][kb + tig + 4]);
                af[mt][3] = f2tf(As[cur][mb + 8][kb + tig + 4]);
            }
            uint32_t bf[8][2];
            #pragma unroll
            for (int nt = 0; nt < 8; nt++) {
                int nb = warp_n * 64 + nt * 8 + gid;
                bf[nt][0] = f2tf(Bs[cur][kb + tig    ][nb]);
                bf[nt][1] = f2tf(Bs[cur][kb + tig + 4][nb]);
            }
            #pragma unroll
            for (int mt = 0; mt < 2; mt++)
                #pragma unroll
                for (int nt = 0; nt < 8; nt++)
                    mma_tf32(acc[mt][nt], af[mt], bf[nt]);
        }
        __syncthreads();
    }
    #pragma unroll
    for (int mt = 0; mt < 2; mt++) {
        int r0 = brow + warp_m * 32 + mt * 16 + gid;
        #pragma unroll
        for (int nt = 0; nt < 8; nt++) {
            int c = bcol + warp_n * 64 + nt * 8 + 2 * tig;
            if (r0 < M)
                *(float2*)&C[(size_t)r0 * FDIM + c] = make_float2(acc[mt][nt][0], acc[mt][nt][1]);
            if (r0 + 8 < M)
                *(float2*)&C[(size_t)(r0 + 8) * FDIM + c] = make_float2(acc[mt][nt][2], acc[mt][nt][3]);
        }
    }
}

// GEMV for W3
__global__ void k_dotw3(const float* __restrict__ act, const float* __restrict__ W3, int N) {
    int warp = (blockIdx.x * blockDim.x + threadIdx.x) >> 5;
    int lane = threadIdx.x & 31;
    if (warp >= N) return;
    const float4* row = (const float4*)&act[(size_t)warp * FDIM];
    const float4* w = (const float4*)W3;
    float4 a = row[lane], b = __ldg(&w[lane]);
    float4 a2 = row[32 + lane], b2 = __ldg(&w[32 + lane]);
    float p = a.x * b.x + a.y * b.y + a.z * b.z + a.w * b.w
            + a2.x * b2.x + a2.y * b2.y + a2.z * b2.z + a2.w * b2.w;
    p = wsum(p);
    if (lane == 0) g_h3[warp] = p;
}

// ---------------- attention coefficients -------------------------------------
__global__ void k_alphas(const float* __restrict__ h, const float* __restrict__ asrc,
                         const float* __restrict__ adst, int N) {
    int warp = (blockIdx.x * blockDim.x + threadIdx.x) >> 5;
    int lane = threadIdx.x & 31;
    if (warp >= N) return;
    const float4* row = (const float4*)&h[(size_t)warp * FDIM];
    const float4* as4 = (const float4*)asrc;
    const float4* ad4 = (const float4*)adst;
    float4 va = row[lane];        // heads 0|1 split at lane 16
    float4 vb = row[32 + lane];   // heads 2|3
    float4 wa = __ldg(&as4[lane]),      wb = __ldg(&as4[32 + lane]);
    float4 da = __ldg(&ad4[lane]),      db = __ldg(&ad4[32 + lane]);
    float pa = va.x * wa.x + va.y * wa.y + va.z * wa.z + va.w * wa.w;
    float pb = vb.x * wb.x + vb.y * wb.y + vb.z * wb.z + vb.w * wb.w;
    float qa = va.x * da.x + va.y * da.y + va.z * da.z + va.w * da.w;
    float qb = vb.x * db.x + vb.y * db.y + vb.z * db.z + vb.w * db.w;
    #pragma unroll
    for (int o = 8; o; o >>= 1) {
        pa += __shfl_xor_sync(0xffffffffu, pa, o);
        pb += __shfl_xor_sync(0xffffffffu, pb, o);
        qa += __shfl_xor_sync(0xffffffffu, qa, o);
        qb += __shfl_xor_sync(0xffffffffu, qb, o);
    }
    if (lane == 0)  { g_alsrc[warp * 4 + 0] = pa; g_alsrc[warp * 4 + 2] = pb;
                      g_aldst[warp * 4 + 0] = qa; g_aldst[warp * 4 + 2] = qb; }
    if (lane == 16) { g_alsrc[warp * 4 + 1] = pa; g_alsrc[warp * 4 + 3] = pb;
                      g_aldst[warp * 4 + 1] = qa; g_aldst[warp * 4 + 3] = qb; }
}

// ---------------- GAT aggregation: 2 warps per dst node (channel halves) -----
// warp gw: node gw>>1, half (gw&1) -> 128 channels = 2 heads.
__global__ __launch_bounds__(256) void k_aggregate(const float* __restrict__ h,
                                                   const float* __restrict__ bias,
                                                   float* __restrict__ out,
                                                   int N, int useElu) {
    int gw = (blockIdx.x * blockDim.x + threadIdx.x) >> 5;
    int lane = threadIdx.x & 31;
    int n = gw >> 1, half = gw & 1;
    if (n >= N) return;
    int e0 = g_off[n], e1 = g_off[n + 1];
    float2 ald = *(const float2*)&g_aldst[n * 4 + half * 2];
    bool lo = lane < 16;

    float4 acc = make_float4(0.f, 0.f, 0.f, 0.f);
    float sE = 0.f, sO = 0.f;
    #pragma unroll 4
    for (int e = e0; e < e1; e++) {
        int sj = __ldg(&g_ssrc[e]);
        float2 as = *(const float2*)&g_alsrc[sj * 4 + half * 2];
        float we = __expf(lrelu(as.x + ald.x));
        float wo = __expf(lrelu(as.y + ald.y));
        sE += we; sO += wo;
        float4 v = __ldg((const float4*)&h[(size_t)sj * FDIM + half * 128] + lane);
        float w = lo ? we : wo;
        acc.x += w * v.x; acc.y += w * v.y; acc.z += w * v.z; acc.w += w * v.w;
    }
    float inv = 1.f / ((lo ? sE : sO) + 1e-16f);
    float4 b = __ldg((const float4*)&bias[half * 128] + lane);
    float4 o;
    o.x = acc.x * inv + b.x; o.y = acc.y * inv + b.y;
    o.z = acc.z * inv + b.z; o.w = acc.w * inv + b.w;
    if (useElu) {
        o.x = o.x > 0.f ? o.x : (__expf(o.x) - 1.f);
        o.y = o.y > 0.f ? o.y : (__expf(o.y) - 1.f);
        o.z = o.z > 0.f ? o.z : (__expf(o.z) - 1.f);
        o.w = o.w > 0.f ? o.w : (__expf(o.w) - 1.f);
    }
    *((float4*)&out[(size_t)n * FDIM + half * 128] + lane) = o;
}

// ---------------- layer 3 aggregation (thread per node) ----------------------
__global__ void k_agg3(const float* __restrict__ asrc3, const float* __restrict__ adst3,
                       const float* __restrict__ b3, float* __restrict__ out, int N) {
    int n = blockIdx.x * blockDim.x + threadIdx.x;
    if (n >= N) return;
    float as = __ldg(&asrc3[0]);
    float hd = g_h3[n] * __ldg(&adst3[0]);
    int e0 = g_off[n], e1 = g_off[n + 1];
    float num = 0.f, den = 0.f;
    #pragma unroll 4
    for (int e = e0; e < e1; e++) {
        float hs = g_h3[__ldg(&g_ssrc[e])];
        float w = __expf(lrelu(hs * as + hd));
        num += w * hs;
        den += w;
    }
    out[n] = num / (den + 1e-16f) + __ldg(&b3[0]);
}

// ---------------- launch -----------------------------------------------------
extern "C" void kernel_launch(void* const* d_in, const int* in_sizes, int n_in,
                              void* d_out, int out_size) {
    const float* x      = (const float*)d_in[0];
    const void*  eidx   = d_in[1];
    const float* W1     = (const float*)d_in[2];
    const float* asrc1  = (const float*)d_in[3];
    const float* adst1  = (const float*)d_in[4];
    const float* b1     = (const float*)d_in[5];
    const float* W2     = (const float*)d_in[6];
    const float* asrc2  = (const float*)d_in[7];
    const float* adst2  = (const float*)d_in[8];
    const float* b2     = (const float*)d_in[9];
    const float* W3     = (const float*)d_in[10];
    const float* asrc3  = (const float*)d_in[11];
    const float* adst3  = (const float*)d_in[12];
    const float* b3     = (const float*)d_in[13];
    float* out = (float*)d_out;

    int N = in_sizes[0] / 128;        // 50000
    int E = in_sizes[1] / 2;          // 650000
    int Etot = E + N;
    int nb = (N + 1023) / 1024;

    dim3 ggrid(FDIM / 128, (N + 127) / 128);
    int eblocks = (Etot + 255) / 256;
    int wblocks  = (N + 7) / 8;            // warp-per-node
    int wblocks2 = (2 * N + 7) / 8;        // 2 warps per node

    k_buildhist<<<eblocks, 256>>>((const long long*)eidx, E, N);   // 1
    k_scanA<<<nb, 1024>>>(N);                                       // 2
    k_scanC<<<(N + 255) / 256, 256>>>(N);                           // 3
    k_gemm<<<ggrid, 256>>>(x, W1, g_feat, N, 128);                  // 4 (profiled)
    k_scatter<<<eblocks, 256>>>(Etot, N);                           // 5

    // layer 1
    k_alphas<<<wblocks, 256>>>(g_feat, asrc1, adst1, N);            // 6
    k_aggregate<<<wblocks2, 256>>>(g_feat, b1, g_act, N, 1);        // 7

    // layer 2
    k_gemm<<<ggrid, 256>>>(g_act, W2, g_feat, N, 256);              // 8
    k_alphas<<<wblocks, 256>>>(g_feat, asrc2, adst2, N);            // 9
    k_aggregate<<<wblocks2, 256>>>(g_feat, b2, g_act, N, 1);        // 10

    // layer 3
    k_dotw3<<<wblocks, 256>>>(g_act, W3, N);                        // 11
    k_agg3<<<(N + 255) / 256, 256>>>(asrc3, adst3, b3, out, N);     // 12

    (void)n_in; (void)out_size;
}

// round 7
// speedup vs baseline: 1.3580x; 1.3580x over previous
#include <cuda_runtime.h>
#include <math.h>
#include <stdint.h>

#define NMAX   50000
#define EMAX   700000     // 650000 edges + 50000 self loops
#define FDIM   256
#define HEADS  4
#define NEG_SLOPE 0.2f

// ---------------- scratch (device globals; no allocation allowed) -----------
__device__ int   g_src [EMAX];
__device__ int   g_dst [EMAX];
__device__ int   g_ssrc[EMAX];
__device__ int   g_deg [NMAX];          // zeroed at load; re-zeroed in k_scatter
__device__ int   g_off [NMAX + 1];
__device__ int   g_cur [NMAX];
__device__ int   g_ticket;
__device__ volatile int g_bflag[64];
__device__ int   g_bval[64];
__device__ __align__(16) float g_S   [NMAX * 512];   // layer-1 weighted-x sums
__device__ __align__(16) float g_feat[NMAX * FDIM];  // layer-2 h
__device__ __align__(16) float g_act [NMAX * FDIM];  // layer outputs
__device__ __align__(16) float g_alsrc[NMAX * HEADS];
__device__ __align__(16) float g_aldst[NMAX * HEADS];
__device__ float g_h3  [NMAX];

// ---------------- helpers ---------------------------------------------------
__device__ __forceinline__ float lrelu(float x) { return x > 0.f ? x : NEG_SLOPE * x; }
__device__ __forceinline__ uint32_t f2tf(float f) {
    uint32_t r;
    asm("cvt.rna.tf32.f32 %0, %1;" : "=r"(r) : "f"(f));
    return r;
}
__device__ __forceinline__ void mma_tf32(float* d, const uint32_t* a, const uint32_t* b) {
    asm volatile(
        "mma.sync.aligned.m16n8k8.row.col.f32.tf32.tf32.f32 "
        "{%0,%1,%2,%3}, {%4,%5,%6,%7}, {%8,%9}, {%0,%1,%2,%3};"
        : "+f"(d[0]), "+f"(d[1]), "+f"(d[2]), "+f"(d[3])
        : "r"(a[0]), "r"(a[1]), "r"(a[2]), "r"(a[3]), "r"(b[0]), "r"(b[1]));
}
__device__ __forceinline__ void cp16z(uint32_t s, const void* g, int sz) {
    asm volatile("cp.async.cg.shared.global [%0], [%1], 16, %2;"
                 :: "r"(s), "l"(g), "r"(sz));
}
__device__ __forceinline__ void cp_commit() { asm volatile("cp.async.commit_group;"); }
__device__ __forceinline__ void cp_wait1()  { asm volatile("cp.async.wait_group 1;"); }

// =============== 1. prep: edge build+hist  ||  layer-1 alphas from x =========
// blocks [0, eblocks): edges.  blocks [eblocks, eblocks+ablocks): alphas.
__global__ __launch_bounds__(256) void k_prep(const long long* __restrict__ e, int E, int N,
                                              const float* __restrict__ x,
                                              const float* __restrict__ W1,
                                              const float* __restrict__ asrc,
                                              const float* __restrict__ adst,
                                              int eblocks) {
    int bid = blockIdx.x, tid = threadIdx.x;
    if (bid < eblocks) {
        if (bid == 0 && tid < 64) {                   // reset scan state per replay
            g_bflag[tid] = 0;
            if (tid == 0) g_ticket = 0;
        }
        int i = bid * 256 + tid;
        bool is64 = true;
        #pragma unroll
        for (int j = 0; j < 8; j++) {
            unsigned long long v = (unsigned long long)__ldg(&e[j * 7 + 1]);
            if (v >= (1ULL << 31)) is64 = false;
        }
        if (i < E) {
            int s, d;
            if (is64) { s = (int)e[i]; d = (int)e[E + i]; }
            else      { const int* p = (const int*)e; s = p[i]; d = p[E + i]; }
            g_src[i] = s; g_dst[i] = d;
            atomicAdd(&g_deg[d], 1);
        } else if (i < E + N) {
            int n = i - E;
            g_src[i] = n; g_dst[i] = n;
            atomicAdd(&g_deg[n], 1);
        }
        return;
    }
    // ----- alpha blocks: project W1 against a_src/a_dst (redundant per block),
    // then per-warp GEMV over x. ws[v][k], v = head*2 + isdst.
    __shared__ float ws[8][128];
    #pragma unroll
    for (int j = 0; j < 4; j++) {
        int idx = tid + j * 256;              // 0..1023
        int v = idx >> 7, k = idx & 127;
        int head = v >> 1;
        const float* avec = (v & 1) ? adst : asrc;
        float s = 0.f;
        #pragma unroll 8
        for (int c = 0; c < 64; c++)
            s += __ldg(&W1[k * 256 + head * 64 + c]) * __ldg(&avec[head * 64 + c]);
        ws[v][k] = s;
    }
    __syncthreads();
    int wid = tid >> 5, lane = tid & 31;
    int n = (bid - eblocks) * 8 + wid;
    if (n >= N) return;
    float4 xv = *(const float4*)&x[(size_t)n * 128 + lane * 4];
    float dot[8];
    #pragma unroll
    for (int v = 0; v < 8; v++) {
        float4 w = *(const float4*)&ws[v][lane * 4];
        dot[v] = xv.x * w.x + xv.y * w.y + xv.z * w.z + xv.w * w.w;
    }
    #pragma unroll
    for (int v = 0; v < 8; v++)
        #pragma unroll
        for (int o = 16; o; o >>= 1) dot[v] += __shfl_xor_sync(0xffffffffu, dot[v], o);
    if (lane == 0) {
        *(float4*)&g_alsrc[n * 4] = make_float4(dot[0], dot[2], dot[4], dot[6]);
        *(float4*)&g_aldst[n * 4] = make_float4(dot[1], dot[3], dot[5], dot[7]);
    }
}

// =============== 2. single-launch chained scan -> g_off, g_cur ===============
__global__ __launch_bounds__(1024) void k_scan(int n) {
    __shared__ int sh[1024];
    __shared__ int s_bid, s_excl;
    int tid = threadIdx.x;
    if (tid == 0) s_bid = atomicAdd(&g_ticket, 1);
    __syncthreads();
    int bid = s_bid;
    int i = bid * 1024 + tid;
    int d = (i < n) ? g_deg[i] : 0;
    sh[tid] = d;
    __syncthreads();
    #pragma unroll
    for (int o = 1; o < 1024; o <<= 1) {
        int t = (tid >= o) ? sh[tid - o] : 0;
        __syncthreads();
        sh[tid] += t;
        __syncthreads();
    }
    if (tid == 0) {
        int excl = 0;
        if (bid > 0) {
            while (g_bflag[bid - 1] != 2) { }
            __threadfence();
            excl = g_bval[bid - 1];
        }
        g_bval[bid] = excl + sh[1023];
        __threadfence();
        g_bflag[bid] = 2;
        s_excl = excl;
    }
    __syncthreads();
    int excl = s_excl;
    if (i < n) {
        int incl = sh[tid] + excl;
        g_off[i + 1] = incl;
        g_cur[i] = incl - d;
    }
    if (i == 0) g_off[0] = 0;
}

// =============== 3. scatter (+ deg reset for next replay) ====================
__global__ void k_scatter(int Etot, int N) {
    int i = blockIdx.x * blockDim.x + threadIdx.x;
    if (i < Etot) {
        int p = atomicAdd(&g_cur[g_dst[i]], 1);
        g_ssrc[p] = g_src[i];
    }
    if (i < N) g_deg[i] = 0;
}

// =============== 4. layer-1 aggregation over RAW x (PROFILED) ================
// warp per node; lane owns 4 x-channels; 4 heads accumulated per lane.
// S[n, h, k] = (1/s_h) * sum_e w_eh * x[src_e, k]
__global__ __launch_bounds__(256) void k_aggX(const float* __restrict__ x, int N) {
    int gw = (blockIdx.x * blockDim.x + threadIdx.x) >> 5;
    int lane = threadIdx.x & 31;
    if (gw >= N) return;
    int e0 = g_off[gw], e1 = g_off[gw + 1];
    float4 ald = *(const float4*)&g_aldst[gw * 4];
    float4 a0 = make_float4(0.f, 0.f, 0.f, 0.f), a1 = a0, a2 = a0, a3 = a0;
    float s0 = 0.f, s1 = 0.f, s2 = 0.f, s3 = 0.f;
    #pragma unroll 2
    for (int e = e0; e < e1; e++) {
        int sj = __ldg(&g_ssrc[e]);
        float4 as = *(const float4*)&g_alsrc[sj * 4];
        float w0 = __expf(lrelu(as.x + ald.x));
        float w1 = __expf(lrelu(as.y + ald.y));
        float w2 = __expf(lrelu(as.z + ald.z));
        float w3 = __expf(lrelu(as.w + ald.w));
        s0 += w0; s1 += w1; s2 += w2; s3 += w3;
        float4 v = __ldg((const float4*)&x[(size_t)sj * 128] + lane);
        a0.x += w0 * v.x; a0.y += w0 * v.y; a0.z += w0 * v.z; a0.w += w0 * v.w;
        a1.x += w1 * v.x; a1.y += w1 * v.y; a1.z += w1 * v.z; a1.w += w1 * v.w;
        a2.x += w2 * v.x; a2.y += w2 * v.y; a2.z += w2 * v.z; a2.w += w2 * v.w;
        a3.x += w3 * v.x; a3.y += w3 * v.y; a3.z += w3 * v.z; a3.w += w3 * v.w;
    }
    float i0 = 1.f / (s0 + 1e-16f), i1 = 1.f / (s1 + 1e-16f);
    float i2 = 1.f / (s2 + 1e-16f), i3 = 1.f / (s3 + 1e-16f);
    float4* Sp = (float4*)&g_S[(size_t)gw * 512];
    Sp[lane]      = make_float4(a0.x * i0, a0.y * i0, a0.z * i0, a0.w * i0);
    Sp[32 + lane] = make_float4(a1.x * i1, a1.y * i1, a1.z * i1, a1.w * i1);
    Sp[64 + lane] = make_float4(a2.x * i2, a2.y * i2, a2.z * i2, a2.w * i2);
    Sp[96 + lane] = make_float4(a3.x * i3, a3.y * i3, a3.z * i3, a3.w * i3);
}

// =============== 5. layer-1 post-GEMM: out = S[:,h] @ W1[:,h] + b, ELU =======
// per head (blockIdx.z): [M,128] @ [128,64]; BM=128 BN=64 BK=16, 256 thr
__global__ __launch_bounds__(256) void k_postgemm(const float* __restrict__ W1,
                                                  const float* __restrict__ b1,
                                                  float* __restrict__ out, int M) {
    __shared__ float As[16][132];
    __shared__ float Bs[16][68];
    int tid = threadIdx.x;
    int h = blockIdx.z;
    int brow = blockIdx.y * 128;
    int tx = tid & 15, ty = tid >> 4;
    float acc[8][4];
    #pragma unroll
    for (int i = 0; i < 8; i++)
        #pragma unroll
        for (int j = 0; j < 4; j++) acc[i][j] = 0.f;

    for (int k0 = 0; k0 < 128; k0 += 16) {
        #pragma unroll
        for (int l = 0; l < 2; l++) {
            int idx = tid + l * 256;
            int r = idx >> 2, kc = (idx & 3) << 2;
            float4 v = make_float4(0.f, 0.f, 0.f, 0.f);
            if (brow + r < M)
                v = *(const float4*)&g_S[(size_t)(brow + r) * 512 + h * 128 + k0 + kc];
            As[kc + 0][r] = v.x; As[kc + 1][r] = v.y;
            As[kc + 2][r] = v.z; As[kc + 3][r] = v.w;
        }
        {
            int r = tid >> 4, c = (tid & 15) << 2;
            *(float4*)&Bs[r][c] = *(const float4*)&W1[(size_t)(k0 + r) * 256 + h * 64 + c];
        }
        __syncthreads();
        #pragma unroll
        for (int k = 0; k < 16; k++) {
            float a[8], b[4];
            #pragma unroll
            for (int i = 0; i < 8; i++) a[i] = As[k][ty * 8 + i];
            #pragma unroll
            for (int j = 0; j < 4; j++) b[j] = Bs[k][tx * 4 + j];
            #pragma unroll
            for (int i = 0; i < 8; i++)
                #pragma unroll
                for (int j = 0; j < 4; j++) acc[i][j] += a[i] * b[j];
        }
        __syncthreads();
    }
    #pragma unroll
    for (int i = 0; i < 8; i++) {
        int row = brow + ty * 8 + i;
        if (row < M) {
            float4 o;
            float b0 = __ldg(&b1[h * 64 + tx * 4 + 0]), bb1 = __ldg(&b1[h * 64 + tx * 4 + 1]);
            float b2 = __ldg(&b1[h * 64 + tx * 4 + 2]), b3 = __ldg(&b1[h * 64 + tx * 4 + 3]);
            o.x = acc[i][0] + b0; o.y = acc[i][1] + bb1;
            o.z = acc[i][2] + b2; o.w = acc[i][3] + b3;
            o.x = o.x > 0.f ? o.x : (__expf(o.x) - 1.f);
            o.y = o.y > 0.f ? o.y : (__expf(o.y) - 1.f);
            o.z = o.z > 0.f ? o.z : (__expf(o.z) - 1.f);
            o.w = o.w > 0.f ? o.w : (__expf(o.w) - 1.f);
            *(float4*)&out[(size_t)row * 256 + h * 64 + tx * 4] = o;
        }
    }
}

// =============== 6. layer-2 GEMM (tf32 MMA + cp.async) =======================
__global__ __launch_bounds__(256) void k_gemm(const float* __restrict__ A,
                                              const float* __restrict__ B,
                                              float* __restrict__ C,
                                              int M, int K) {
    __shared__ float As[2][128][20];
    __shared__ float Bs[2][16][136];
    int tid = threadIdx.x;
    int lane = tid & 31, wid = tid >> 5;
    int gid = lane >> 2, tig = lane & 3;
    int warp_m = wid >> 1, warp_n = wid & 1;
    int brow = blockIdx.y * 128, bcol = blockIdx.x * 128;

    int ar0 = tid >> 2,          ak0 = (tid & 3) << 2;
    int ar1 = (tid + 256) >> 2,  ak1 = ((tid + 256) & 3) << 2;
    int bk0 = tid >> 5,          bn0 = (tid & 31) << 2;
    int bk1 = (tid + 256) >> 5,  bn1 = ((tid + 256) & 31) << 2;
    bool av0 = (brow + ar0) < M, av1 = (brow + ar1) < M;
    const float* Ar0 = A + (size_t)(av0 ? brow + ar0 : 0) * K + ak0;
    const float* Ar1 = A + (size_t)(av1 ? brow + ar1 : 0) * K + ak1;
    const float* Br0 = B + (size_t)bk0 * FDIM + bcol + bn0;
    const float* Br1 = B + (size_t)bk1 * FDIM + bcol + bn1;

    uint32_t sa0[2], sa1[2], sb0[2], sb1[2];
    #pragma unroll
    for (int s = 0; s < 2; s++) {
        sa0[s] = (uint32_t)__cvta_generic_to_shared(&As[s][ar0][ak0]);
        sa1[s] = (uint32_t)__cvta_generic_to_shared(&As[s][ar1][ak1]);
        sb0[s] = (uint32_t)__cvta_generic_to_shared(&Bs[s][bk0][bn0]);
        sb1[s] = (uint32_t)__cvta_generic_to_shared(&Bs[s][bk1][bn1]);
    }

    float acc[2][8][4];
    #pragma unroll
    for (int mt = 0; mt < 2; mt++)
        #pragma unroll
        for (int nt = 0; nt < 8; nt++)
            #pragma unroll
            for (int q = 0; q < 4; q++) acc[mt][nt][q] = 0.f;

    int ntile = K >> 4;
    cp16z(sa0[0], Ar0, av0 ? 16 : 0);
    cp16z(sa1[0], Ar1, av1 ? 16 : 0);
    cp16z(sb0[0], Br0, 16);
    cp16z(sb1[0], Br1, 16);
    cp_commit();

    for (int t = 0; t < ntile; t++) {
        int nxt = t + 1;
        if (nxt < ntile) {
            int slot = nxt & 1;
            cp16z(sa0[slot], Ar0 + nxt * 16, av0 ? 16 : 0);
            cp16z(sa1[slot], Ar1 + nxt * 16, av1 ? 16 : 0);
            cp16z(sb0[slot], Br0 + (size_t)nxt * 16 * FDIM, 16);
            cp16z(sb1[slot], Br1 + (size_t)nxt * 16 * FDIM, 16);
        }
        cp_commit();
        cp_wait1();
        __syncthreads();
        int cur = t & 1;
        #pragma unroll
        for (int k8 = 0; k8 < 2; k8++) {
            int kb = k8 * 8;
            uint32_t af[2][4];
            #pragma unroll
            for (int mt = 0; mt < 2; mt++) {
                int mb = warp_m * 32 + mt * 16 + gid;
                af[mt][0] = f2tf(As[cur][mb    ][kb + tig]);
                af[mt][1] = f2tf(As[cur][mb + 8][kb + tig]);
                af[mt][2] = f2tf(As[cur][mb    ][kb + tig + 4]);
                af[mt][3] = f2tf(As[cur][mb + 8][kb + tig + 4]);
            }
            uint32_t bf[8][2];
            #pragma unroll
            for (int nt = 0; nt < 8; nt++) {
                int nb = warp_n * 64 + nt * 8 + gid;
                bf[nt][0] = f2tf(Bs[cur][kb + tig    ][nb]);
                bf[nt][1] = f2tf(Bs[cur][kb + tig + 4][nb]);
            }
            #pragma unroll
            for (int mt = 0; mt < 2; mt++)
                #pragma unroll
                for (int nt = 0; nt < 8; nt++)
                    mma_tf32(acc[mt][nt], af[mt], bf[nt]);
        }
        __syncthreads();
    }
    #pragma unroll
    for (int mt = 0; mt < 2; mt++) {
        int r0 = brow + warp_m * 32 + mt * 16 + gid;
        #pragma unroll
        for (int nt = 0; nt < 8; nt++) {
            int c = bcol + warp_n * 64 + nt * 8 + 2 * tig;
            if (r0 < M)
                *(float2*)&C[(size_t)r0 * FDIM + c] = make_float2(acc[mt][nt][0], acc[mt][nt][1]);
            if (r0 + 8 < M)
                *(float2*)&C[(size_t)(r0 + 8) * FDIM + c] = make_float2(acc[mt][nt][2], acc[mt][nt][3]);
        }
    }
}

// =============== 7. layer-2 alphas ===========================================
__global__ void k_alphas(const float* __restrict__ h, const float* __restrict__ asrc,
                         const float* __restrict__ adst, int N) {
    int warp = (blockIdx.x * blockDim.x + threadIdx.x) >> 5;
    int lane = threadIdx.x & 31;
    if (warp >= N) return;
    const float4* row = (const float4*)&h[(size_t)warp * FDIM];
    const float4* as4 = (const float4*)asrc;
    const float4* ad4 = (const float4*)adst;
    float4 va = row[lane];
    float4 vb = row[32 + lane];
    float4 wa = __ldg(&as4[lane]),      wb = __ldg(&as4[32 + lane]);
    float4 da = __ldg(&ad4[lane]),      db = __ldg(&ad4[32 + lane]);
    float pa = va.x * wa.x + va.y * wa.y + va.z * wa.z + va.w * wa.w;
    float pb = vb.x * wb.x + vb.y * wb.y + vb.z * wb.z + vb.w * wb.w;
    float qa = va.x * da.x + va.y * da.y + va.z * da.z + va.w * da.w;
    float qb = vb.x * db.x + vb.y * db.y + vb.z * db.z + vb.w * db.w;
    #pragma unroll
    for (int o = 8; o; o >>= 1) {
        pa += __shfl_xor_sync(0xffffffffu, pa, o);
        pb += __shfl_xor_sync(0xffffffffu, pb, o);
        qa += __shfl_xor_sync(0xffffffffu, qa, o);
        qb += __shfl_xor_sync(0xffffffffu, qb, o);
    }
    if (lane == 0)  { g_alsrc[warp * 4 + 0] = pa; g_alsrc[warp * 4 + 2] = pb;
                      g_aldst[warp * 4 + 0] = qa; g_aldst[warp * 4 + 2] = qb; }
    if (lane == 16) { g_alsrc[warp * 4 + 1] = pa; g_alsrc[warp * 4 + 3] = pb;
                      g_aldst[warp * 4 + 1] = qa; g_aldst[warp * 4 + 3] = qb; }
}

// =============== 8. layer-2 aggregation (2 warps per node) ===================
__global__ __launch_bounds__(256) void k_aggregate(const float* __restrict__ h,
                                                   const float* __restrict__ bias,
                                                   float* __restrict__ out, int N) {
    int gw = (blockIdx.x * blockDim.x + threadIdx.x) >> 5;
    int lane = threadIdx.x & 31;
    int n = gw >> 1, half = gw & 1;
    if (n >= N) return;
    int e0 = g_off[n], e1 = g_off[n + 1];
    float2 ald = *(const float2*)&g_aldst[n * 4 + half * 2];
    bool lo = lane < 16;

    float4 acc = make_float4(0.f, 0.f, 0.f, 0.f);
    float sE = 0.f, sO = 0.f;
    #pragma unroll 4
    for (int e = e0; e < e1; e++) {
        int sj = __ldg(&g_ssrc[e]);
        float2 as = *(const float2*)&g_alsrc[sj * 4 + half * 2];
        float we = __expf(lrelu(as.x + ald.x));
        float wo = __expf(lrelu(as.y + ald.y));
        sE += we; sO += wo;
        float4 v = __ldg((const float4*)&h[(size_t)sj * FDIM + half * 128] + lane);
        float w = lo ? we : wo;
        acc.x += w * v.x; acc.y += w * v.y; acc.z += w * v.z; acc.w += w * v.w;
    }
    float inv = 1.f / ((lo ? sE : sO) + 1e-16f);
    float4 b = __ldg((const float4*)&bias[half * 128] + lane);
    float4 o;
    o.x = acc.x * inv + b.x; o.y = acc.y * inv + b.y;
    o.z = acc.z * inv + b.z; o.w = acc.w * inv + b.w;
    o.x = o.x > 0.f ? o.x : (__expf(o.x) - 1.f);
    o.y = o.y > 0.f ? o.y : (__expf(o.y) - 1.f);
    o.z = o.z > 0.f ? o.z : (__expf(o.z) - 1.f);
    o.w = o.w > 0.f ? o.w : (__expf(o.w) - 1.f);
    *((float4*)&out[(size_t)n * FDIM + half * 128] + lane) = o;
}

// =============== 9/10. layer 3 ==============================================
__global__ void k_dotw3(const float* __restrict__ act, const float* __restrict__ W3, int N) {
    int warp = (blockIdx.x * blockDim.x + threadIdx.x) >> 5;
    int lane = threadIdx.x & 31;
    if (warp >= N) return;
    const float4* row = (const float4*)&act[(size_t)warp * FDIM];
    const float4* w = (const float4*)W3;
    float4 a = row[lane], b = __ldg(&w[lane]);
    float4 a2 = row[32 + lane], b2 = __ldg(&w[32 + lane]);
    float p = a.x * b.x + a.y * b.y + a.z * b.z + a.w * b.w
            + a2.x * b2.x + a2.y * b2.y + a2.z * b2.z + a2.w * b2.w;
    #pragma unroll
    for (int o = 16; o; o >>= 1) p += __shfl_xor_sync(0xffffffffu, p, o);
    if (lane == 0) g_h3[warp] = p;
}

__global__ void k_agg3(const float* __restrict__ asrc3, const float* __restrict__ adst3,
                       const float* __restrict__ b3, float* __restrict__ out, int N) {
    int n = blockIdx.x * blockDim.x + threadIdx.x;
    if (n >= N) return;
    float as = __ldg(&asrc3[0]);
    float hd = g_h3[n] * __ldg(&adst3[0]);
    int e0 = g_off[n], e1 = g_off[n + 1];
    float num = 0.f, den = 0.f;
    #pragma unroll 4
    for (int e = e0; e < e1; e++) {
        float hs = g_h3[__ldg(&g_ssrc[e])];
        float w = __expf(lrelu(hs * as + hd));
        num += w * hs;
        den += w;
    }
    out[n] = num / (den + 1e-16f) + __ldg(&b3[0]);
}

// ---------------- launch -----------------------------------------------------
extern "C" void kernel_launch(void* const* d_in, const int* in_sizes, int n_in,
                              void* d_out, int out_size) {
    const float* x      = (const float*)d_in[0];
    const void*  eidx   = d_in[1];
    const float* W1     = (const float*)d_in[2];
    const float* asrc1  = (const float*)d_in[3];
    const float* adst1  = (const float*)d_in[4];
    const float* b1     = (const float*)d_in[5];
    const float* W2     = (const float*)d_in[6];
    const float* asrc2  = (const float*)d_in[7];
    const float* adst2  = (const float*)d_in[8];
    const float* b2     = (const float*)d_in[9];
    const float* W3     = (const float*)d_in[10];
    const float* asrc3  = (const float*)d_in[11];
    const float* adst3  = (const float*)d_in[12];
    const float* b3     = (const float*)d_in[13];
    float* out = (float*)d_out;

    int N = in_sizes[0] / 128;        // 50000
    int E = in_sizes[1] / 2;          // 650000
    int Etot = E + N;
    int nb = (N + 1023) / 1024;

    int eblocks = (Etot + 255) / 256;
    int ablocks = (N + 7) / 8;
    int wblocks  = (N + 7) / 8;
    int wblocks2 = (2 * N + 7) / 8;
    dim3 ggrid(FDIM / 128, (N + 127) / 128);
    dim3 pgrid(1, (N + 127) / 128, HEADS);

    // 1-3: prerequisites (prep = build+hist+alphas1; scan; scatter)
    k_prep<<<eblocks + ablocks, 256>>>((const long long*)eidx, E, N,
                                       x, W1, asrc1, adst1, eblocks);
    k_scan<<<nb, 1024>>>(N);
    k_scatter<<<eblocks, 256>>>(Etot, N);
    // 4: layer-1 aggregation over raw x  <-- PROFILED SLOT
    k_aggX<<<wblocks, 256>>>(x, N);
    // 5: layer-1 post-GEMM (+bias+ELU)
    k_postgemm<<<pgrid, 256>>>(W1, b1, g_act, N);
    // 6-8: layer 2
    k_gemm<<<ggrid, 256>>>(g_act, W2, g_feat, N, 256);
    k_alphas<<<wblocks, 256>>>(g_feat, asrc2, adst2, N);
    k_aggregate<<<wblocks2, 256>>>(g_feat, b2, g_act, N);
    // 9-10: layer 3
    k_dotw3<<<wblocks, 256>>>(g_act, W3, N);
    k_agg3<<<(N + 255) / 256, 256>>>(asrc3, adst3, b3, out, N);

    (void)n_in; (void)out_size;
}

// round 13
// speedup vs baseline: 4.3518x; 3.2045x over previous
#include <cuda_runtime.h>
#include <math.h>
#include <stdint.h>

#define NMAX   50000
#define EMAX   700000     // 650000 edges + 50000 self loops
#define FDIM   256
#define HEADS  4
#define NEG_SLOPE 0.2f

// ------- scratch: device globals, ONLY ever accessed inside kernels ---------
// (passing these as kernel args from host passes the HOST shadow under ATS —
//  that was the root cause of R8-R12 failures and the session's slowness)
__device__ int   g_src [EMAX];
__device__ int   g_dst [EMAX];
__device__ int   g_ssrc[EMAX];
__device__ int   g_deg [NMAX];
__device__ int   g_off [NMAX + 1];
__device__ int   g_cur [NMAX];
__device__ int   g_ticket;
__device__ volatile int g_bflag[64];
__device__ int   g_bval[64];
__device__ __align__(16) float g_S   [NMAX * 512];   // layer-1 weighted-x sums
__device__ __align__(16) float g_feat[NMAX * FDIM];  // layer-2 h (pre-attention)
__device__ __align__(16) float g_act [NMAX * FDIM];  // layer activations
__device__ __align__(16) float g_alsrc[NMAX * HEADS];
__device__ __align__(16) float g_aldst[NMAX * HEADS];
__device__ float g_h3  [NMAX];

__device__ __forceinline__ float lrelu(float x) { return x > 0.f ? x : NEG_SLOPE * x; }

// =============== 1. prep: edge build+hist  ||  layer-1 alphas from x =========
__global__ __launch_bounds__(256) void k_prep(const long long* __restrict__ e, int E, int N,
                                              const float* __restrict__ x,
                                              const float* __restrict__ W1,
                                              const float* __restrict__ asrc,
                                              const float* __restrict__ adst,
                                              int eblocks) {
    int bid = blockIdx.x, tid = threadIdx.x;
    if (bid < eblocks) {
        if (bid == 0 && tid < 64) {                   // reset scan state per replay
            g_bflag[tid] = 0;
            if (tid == 0) g_ticket = 0;
        }
        int i = bid * 256 + tid;
        bool is64 = true;
        #pragma unroll
        for (int j = 0; j < 8; j++) {
            unsigned long long v = (unsigned long long)__ldg(&e[j * 7 + 1]);
            if (v >= (1ULL << 31)) is64 = false;
        }
        if (i < E) {
            int s, d;
            if (is64) { s = (int)e[i]; d = (int)e[E + i]; }
            else      { const int* p = (const int*)e; s = p[i]; d = p[E + i]; }
            g_src[i] = s; g_dst[i] = d;
            atomicAdd(&g_deg[d], 1);
        } else if (i < E + N) {
            int n = i - E;
            g_src[i] = n; g_dst[i] = n;
            atomicAdd(&g_deg[n], 1);
        }
        return;
    }
    // alpha blocks: project W1 against a_src/a_dst, then per-warp GEMV over x
    __shared__ float ws[8][128];
    #pragma unroll
    for (int j = 0; j < 4; j++) {
        int idx = tid + j * 256;
        int v = idx >> 7, k = idx & 127;
        int head = v >> 1;
        const float* avec = (v & 1) ? adst : asrc;
        float s = 0.f;
        #pragma unroll 8
        for (int c = 0; c < 64; c++)
            s += __ldg(&W1[k * 256 + head * 64 + c]) * __ldg(&avec[head * 64 + c]);
        ws[v][k] = s;
    }
    __syncthreads();
    int wid = tid >> 5, lane = tid & 31;
    int n = (bid - eblocks) * 8 + wid;
    if (n >= N) return;
    float4 xv = *(const float4*)&x[(size_t)n * 128 + lane * 4];
    float dot[8];
    #pragma unroll
    for (int v = 0; v < 8; v++) {
        float4 w = *(const float4*)&ws[v][lane * 4];
        dot[v] = xv.x * w.x + xv.y * w.y + xv.z * w.z + xv.w * w.w;
    }
    #pragma unroll
    for (int v = 0; v < 8; v++)
        #pragma unroll
        for (int o = 16; o; o >>= 1) dot[v] += __shfl_xor_sync(0xffffffffu, dot[v], o);
    if (lane == 0) {
        *(float4*)&g_alsrc[n * 4] = make_float4(dot[0], dot[2], dot[4], dot[6]);
        *(float4*)&g_aldst[n * 4] = make_float4(dot[1], dot[3], dot[5], dot[7]);
    }
}

// =============== 2. single-launch chained scan -> g_off, g_cur ===============
__global__ __launch_bounds__(1024) void k_scan(int n) {
    __shared__ int sh[1024];
    __shared__ int s_bid, s_excl;
    int tid = threadIdx.x;
    if (tid == 0) s_bid = atomicAdd(&g_ticket, 1);
    __syncthreads();
    int bid = s_bid;
    int i = bid * 1024 + tid;
    int d = (i < n) ? g_deg[i] : 0;
    sh[tid] = d;
    __syncthreads();
    #pragma unroll
    for (int o = 1; o < 1024; o <<= 1) {
        int t = (tid >= o) ? sh[tid - o] : 0;
        __syncthreads();
        sh[tid] += t;
        __syncthreads();
    }
    if (tid == 0) {
        int excl = 0;
        if (bid > 0) {
            while (g_bflag[bid - 1] != 2) { }
            __threadfence();
            excl = g_bval[bid - 1];
        }
        g_bval[bid] = excl + sh[1023];
        __threadfence();
        g_bflag[bid] = 2;
        s_excl = excl;
    }
    __syncthreads();
    int excl = s_excl;
    if (i < n) {
        int incl = sh[tid] + excl;
        g_off[i + 1] = incl;
        g_cur[i] = incl - d;
    }
    if (i == 0) g_off[0] = 0;
}

// =============== 3. scatter (+ deg reset for next replay) ====================
__global__ void k_scatter(int Etot, int N) {
    int i = blockIdx.x * blockDim.x + threadIdx.x;
    if (i < Etot) {
        int p = atomicAdd(&g_cur[g_dst[i]], 1);
        g_ssrc[p] = g_src[i];
    }
    if (i < N) g_deg[i] = 0;
}

// =============== 4. layer-1 aggregation over raw x (PROFILED) ================
__global__ __launch_bounds__(256) void k_aggX(const float* __restrict__ x, int N) {
    int gw = (blockIdx.x * blockDim.x + threadIdx.x) >> 5;
    int lane = threadIdx.x & 31;
    if (gw >= N) return;
    int e0 = g_off[gw], e1 = g_off[gw + 1];
    float4 ald = *(const float4*)&g_aldst[gw * 4];
    float4 a0 = make_float4(0.f, 0.f, 0.f, 0.f), a1 = a0, a2 = a0, a3 = a0;
    float s0 = 0.f, s1 = 0.f, s2 = 0.f, s3 = 0.f;
    #pragma unroll 2
    for (int e = e0; e < e1; e++) {
        int sj = __ldg(&g_ssrc[e]);
        float4 as = *(const float4*)&g_alsrc[sj * 4];
        float w0 = __expf(lrelu(as.x + ald.x));
        float w1 = __expf(lrelu(as.y + ald.y));
        float w2 = __expf(lrelu(as.z + ald.z));
        float w3 = __expf(lrelu(as.w + ald.w));
        s0 += w0; s1 += w1; s2 += w2; s3 += w3;
        float4 v = __ldg((const float4*)&x[(size_t)sj * 128] + lane);
        a0.x += w0 * v.x; a0.y += w0 * v.y; a0.z += w0 * v.z; a0.w += w0 * v.w;
        a1.x += w1 * v.x; a1.y += w1 * v.y; a1.z += w1 * v.z; a1.w += w1 * v.w;
        a2.x += w2 * v.x; a2.y += w2 * v.y; a2.z += w2 * v.z; a2.w += w2 * v.w;
        a3.x += w3 * v.x; a3.y += w3 * v.y; a3.z += w3 * v.z; a3.w += w3 * v.w;
    }
    float i0 = 1.f / (s0 + 1e-16f), i1 = 1.f / (s1 + 1e-16f);
    float i2 = 1.f / (s2 + 1e-16f), i3 = 1.f / (s3 + 1e-16f);
    float4* Sp = (float4*)&g_S[(size_t)gw * 512];
    Sp[lane]      = make_float4(a0.x * i0, a0.y * i0, a0.z * i0, a0.w * i0);
    Sp[32 + lane] = make_float4(a1.x * i1, a1.y * i1, a1.z * i1, a1.w * i1);
    Sp[64 + lane] = make_float4(a2.x * i2, a2.y * i2, a2.z * i2, a2.w * i2);
    Sp[96 + lane] = make_float4(a3.x * i3, a3.y * i3, a3.z * i3, a3.w * i3);
}

// =============== 5. layer-1 post-GEMV: g_act = S @ W1 + b1, ELU ==============
// warp per node; lane owns channels c = lane + 32*j; head(c) = c>>6.
__global__ __launch_bounds__(256) void k_postgemv(const float* __restrict__ W1,
                                                  const float* __restrict__ b1, int N) {
    int gw = (blockIdx.x * blockDim.x + threadIdx.x) >> 5;
    int lane = threadIdx.x & 31;
    if (gw >= N) return;
    const float* S = &g_S[(size_t)gw * 512];
    float acc[8] = {0.f, 0.f, 0.f, 0.f, 0.f, 0.f, 0.f, 0.f};
    #pragma unroll 4
    for (int k = 0; k < 128; k++) {
        float s0 = S[k];
        float s1 = S[128 + k];
        float s2 = S[256 + k];
        float s3 = S[384 + k];
        const float* wr = &W1[(size_t)k * 256 + lane];
        acc[0] += s0 * __ldg(wr);
        acc[1] += s0 * __ldg(wr + 32);
        acc[2] += s1 * __ldg(wr + 64);
        acc[3] += s1 * __ldg(wr + 96);
        acc[4] += s2 * __ldg(wr + 128);
        acc[5] += s2 * __ldg(wr + 160);
        acc[6] += s3 * __ldg(wr + 192);
        acc[7] += s3 * __ldg(wr + 224);
    }
    #pragma unroll
    for (int j = 0; j < 8; j++) {
        int c = lane + 32 * j;
        float o = acc[j] + __ldg(&b1[c]);
        o = o > 0.f ? o : (__expf(o) - 1.f);
        g_act[(size_t)gw * 256 + c] = o;
    }
}

// =============== 6. layer-2 GEMV: g_feat = g_act @ W2 ========================
__global__ __launch_bounds__(256) void k_gemv2(const float* __restrict__ W2, int N) {
    int gw = (blockIdx.x * blockDim.x + threadIdx.x) >> 5;
    int lane = threadIdx.x & 31;
    if (gw >= N) return;
    const float* arow = &g_act[(size_t)gw * 256];
    float acc[8] = {0.f, 0.f, 0.f, 0.f, 0.f, 0.f, 0.f, 0.f};
    #pragma unroll 4
    for (int k = 0; k < 256; k++) {
        float a = arow[k];
        const float* wr = &W2[(size_t)k * 256 + lane];
        #pragma unroll
        for (int j = 0; j < 8; j++) acc[j] += a * __ldg(&wr[32 * j]);
    }
    #pragma unroll
    for (int j = 0; j < 8; j++)
        g_feat[(size_t)gw * 256 + lane + 32 * j] = acc[j];
}

// =============== 7. layer-2 alphas (reads g_feat internally) =================
__global__ void k_alphas(const float* __restrict__ asrc,
                         const float* __restrict__ adst, int N) {
    int warp = (blockIdx.x * blockDim.x + threadIdx.x) >> 5;
    int lane = threadIdx.x & 31;
    if (warp >= N) return;
    const float4* row = (const float4*)&g_feat[(size_t)warp * FDIM];
    const float4* as4 = (const float4*)asrc;
    const float4* ad4 = (const float4*)adst;
    float4 va = row[lane];        // heads 0|1 split at lane 16
    float4 vb = row[32 + lane];   // heads 2|3
    float4 wa = __ldg(&as4[lane]),      wb = __ldg(&as4[32 + lane]);
    float4 da = __ldg(&ad4[lane]),      db = __ldg(&ad4[32 + lane]);
    float pa = va.x * wa.x + va.y * wa.y + va.z * wa.z + va.w * wa.w;
    float pb = vb.x * wb.x + vb.y * wb.y + vb.z * wb.z + vb.w * wb.w;
    float qa = va.x * da.x + va.y * da.y + va.z * da.z + va.w * da.w;
    float qb = vb.x * db.x + vb.y * db.y + vb.z * db.z + vb.w * db.w;
    #pragma unroll
    for (int o = 8; o; o >>= 1) {
        pa += __shfl_xor_sync(0xffffffffu, pa, o);
        pb += __shfl_xor_sync(0xffffffffu, pb, o);
        qa += __shfl_xor_sync(0xffffffffu, qa, o);
        qb += __shfl_xor_sync(0xffffffffu, qb, o);
    }
    if (lane == 0)  { g_alsrc[warp * 4 + 0] = pa; g_alsrc[warp * 4 + 2] = pb;
                      g_aldst[warp * 4 + 0] = qa; g_aldst[warp * 4 + 2] = qb; }
    if (lane == 16) { g_alsrc[warp * 4 + 1] = pa; g_alsrc[warp * 4 + 3] = pb;
                      g_aldst[warp * 4 + 1] = qa; g_aldst[warp * 4 + 3] = qb; }
}

// =============== 8. layer-2 aggregation (2 warps/node, writes g_act) =========
__global__ __launch_bounds__(256) void k_aggregate(const float* __restrict__ bias, int N) {
    int gw = (blockIdx.x * blockDim.x + threadIdx.x) >> 5;
    int lane = threadIdx.x & 31;
    int n = gw >> 1, half = gw & 1;
    if (n >= N) return;
    int e0 = g_off[n], e1 = g_off[n + 1];
    float2 ald = *(const float2*)&g_aldst[n * 4 + half * 2];
    bool lo = lane < 16;

    float4 acc = make_float4(0.f, 0.f, 0.f, 0.f);
    float sE = 0.f, sO = 0.f;
    #pragma unroll 4
    for (int e = e0; e < e1; e++) {
        int sj = __ldg(&g_ssrc[e]);
        float2 as = *(const float2*)&g_alsrc[sj * 4 + half * 2];
        float we = __expf(lrelu(as.x + ald.x));
        float wo = __expf(lrelu(as.y + ald.y));
        sE += we; sO += wo;
        float4 v = __ldg((const float4*)&g_feat[(size_t)sj * FDIM + half * 128] + lane);
        float w = lo ? we : wo;
        acc.x += w * v.x; acc.y += w * v.y; acc.z += w * v.z; acc.w += w * v.w;
    }
    float inv = 1.f / ((lo ? sE : sO) + 1e-16f);
    float4 b = __ldg((const float4*)&bias[half * 128] + lane);
    float4 o;
    o.x = acc.x * inv + b.x; o.y = acc.y * inv + b.y;
    o.z = acc.z * inv + b.z; o.w = acc.w * inv + b.w;
    o.x = o.x > 0.f ? o.x : (__expf(o.x) - 1.f);
    o.y = o.y > 0.f ? o.y : (__expf(o.y) - 1.f);
    o.z = o.z > 0.f ? o.z : (__expf(o.z) - 1.f);
    o.w = o.w > 0.f ? o.w : (__expf(o.w) - 1.f);
    *((float4*)&g_act[(size_t)n * FDIM + half * 128] + lane) = o;
}

// =============== 9. W3 GEMV (reads g_act internally) =========================
__global__ void k_dotw3(const float* __restrict__ W3, int N) {
    int warp = (blockIdx.x * blockDim.x + threadIdx.x) >> 5;
    int lane = threadIdx.x & 31;
    if (warp >= N) return;
    const float4* row = (const float4*)&g_act[(size_t)warp * FDIM];
    const float4* w = (const float4*)W3;
    float4 a = row[lane], b = __ldg(&w[lane]);
    float4 a2 = row[32 + lane], b2 = __ldg(&w[32 + lane]);
    float p = a.x * b.x + a.y * b.y + a.z * b.z + a.w * b.w
            + a2.x * b2.x + a2.y * b2.y + a2.z * b2.z + a2.w * b2.w;
    #pragma unroll
    for (int o = 16; o; o >>= 1) p += __shfl_xor_sync(0xffffffffu, p, o);
    if (lane == 0) g_h3[warp] = p;
}

// =============== 10. layer-3 aggregation -> d_out ============================
__global__ void k_agg3(const float* __restrict__ asrc3, const float* __restrict__ adst3,
                       const float* __restrict__ b3, float* __restrict__ out, int N) {
    int n = blockIdx.x * blockDim.x + threadIdx.x;
    if (n >= N) return;
    float as = __ldg(&asrc3[0]);
    float hd = g_h3[n] * __ldg(&adst3[0]);
    int e0 = g_off[n], e1 = g_off[n + 1];
    float num = 0.f, den = 0.f;
    #pragma unroll 4
    for (int e = e0; e < e1; e++) {
        float hs = g_h3[__ldg(&g_ssrc[e])];
        float w = __expf(lrelu(hs * as + hd));
        num += w * hs;
        den += w;
    }
    out[n] = num / (den + 1e-16f) + __ldg(&b3[0]);
}

// ---------------- launch: ONLY harness pointers cross the boundary ----------
extern "C" void kernel_launch(void* const* d_in, const int* in_sizes, int n_in,
                              void* d_out, int out_size) {
    const float* x      = (const float*)d_in[0];
    const void*  eidx   = d_in[1];
    const float* W1     = (const float*)d_in[2];
    const float* asrc1  = (const float*)d_in[3];
    const float* adst1  = (const float*)d_in[4];
    const float* b1     = (const float*)d_in[5];
    const float* W2     = (const float*)d_in[6];
    const float* asrc2  = (const float*)d_in[7];
    const float* adst2  = (const float*)d_in[8];
    const float* b2     = (const float*)d_in[9];
    const float* W3     = (const float*)d_in[10];
    const float* asrc3  = (const float*)d_in[11];
    const float* adst3  = (const float*)d_in[12];
    const float* b3     = (const float*)d_in[13];
    float* out = (float*)d_out;

    int N = in_sizes[0] / 128;        // 50000
    int E = in_sizes[1] / 2;          // 650000
    int Etot = E + N;
    int nb = (N + 1023) / 1024;

    int eblocks = (Etot + 255) / 256;
    int ablocks = (N + 7) / 8;
    int wblocks  = (N + 7) / 8;            // warp per node
    int wblocks2 = (2 * N + 7) / 8;        // 2 warps per node

    k_prep<<<eblocks + ablocks, 256>>>((const long long*)eidx, E, N,
                                       x, W1, asrc1, adst1, eblocks);      // 1
    k_scan<<<nb, 1024>>>(N);                                                // 2
    k_scatter<<<eblocks, 256>>>(Etot, N);                                   // 3
    k_aggX<<<wblocks, 256>>>(x, N);                                         // 4 (profiled)
    k_postgemv<<<wblocks, 256>>>(W1, b1, N);                                // 5
    k_gemv2<<<wblocks, 256>>>(W2, N);                                       // 6
    k_alphas<<<wblocks, 256>>>(asrc2, adst2, N);                            // 7
    k_aggregate<<<wblocks2, 256>>>(b2, N);                                  // 8
    k_dotw3<<<wblocks, 256>>>(W3, N);                                       // 9
    k_agg3<<<(N + 255) / 256, 256>>>(asrc3, adst3, b3, out, N);             // 10

    (void)n_in; (void)out_size;
}

// round 14
// speedup vs baseline: 11.3806x; 2.6151x over previous
#include <cuda_runtime.h>
#include <math.h>
#include <stdint.h>

#define NMAX   50000
#define EMAX   700000     // 650000 edges + 50000 self loops
#define FDIM   256
#define HEADS  4
#define NEG_SLOPE 0.2f

// ------- scratch: device globals, ONLY ever accessed inside kernels ---------
// (NEVER pass these as kernel args: host-side shadow + ATS = silent host-mem
//  traffic and split-brain buffers — the R8-R12 root cause)
__device__ int   g_src [EMAX];
__device__ int   g_dst [EMAX];
__device__ int   g_ssrc[EMAX];
__device__ int   g_deg [NMAX];
__device__ int   g_off [NMAX + 1];
__device__ int   g_cur [NMAX];
__device__ int   g_ticket;
__device__ volatile int g_bflag[64];
__device__ int   g_bval[64];
__device__ __align__(16) float g_ws  [8 * 128];      // W1-projected alpha vectors
__device__ __align__(16) float g_S   [NMAX * 512];   // layer-1 weighted-x sums
__device__ __align__(16) float g_feat[NMAX * FDIM];  // layer-2 h (pre-attention)
__device__ __align__(16) float g_act [NMAX * FDIM];  // layer activations
__device__ __align__(16) float g_alsrc[NMAX * HEADS];
__device__ __align__(16) float g_aldst[NMAX * HEADS];
__device__ float g_h3  [NMAX];

__device__ __forceinline__ float lrelu(float x) { return x > 0.f ? x : NEG_SLOPE * x; }

// =============== 0. ws projection (one block): g_ws[v][k] ====================
// v = head*2 + isdst;  g_ws[v][k] = sum_c W1[k*256 + head*64 + c] * avec[head*64+c]
__global__ void k_ws(const float* __restrict__ W1,
                     const float* __restrict__ asrc,
                     const float* __restrict__ adst) {
    int wid = threadIdx.x >> 5, lane = threadIdx.x & 31;
    int v = wid, head = v >> 1;
    const float* avec = (v & 1) ? adst : asrc;
    float a0 = __ldg(&avec[head * 64 + lane]);
    float a1 = __ldg(&avec[head * 64 + 32 + lane]);
    for (int k = 0; k < 128; k++) {
        float s = __ldg(&W1[k * 256 + head * 64 + lane]) * a0
                + __ldg(&W1[k * 256 + head * 64 + 32 + lane]) * a1;
        #pragma unroll
        for (int o = 16; o; o >>= 1) s += __shfl_xor_sync(0xffffffffu, s, o);
        if (lane == 0) g_ws[v * 128 + k] = s;
    }
}

// =============== 1. prep: edge build+hist  ||  layer-1 alphas from x =========
__global__ __launch_bounds__(256) void k_prep(const long long* __restrict__ e, int E, int N,
                                              const float* __restrict__ x, int eblocks) {
    int bid = blockIdx.x, tid = threadIdx.x;
    if (bid < eblocks) {
        if (bid == 0 && tid < 64) {                   // reset scan state per replay
            g_bflag[tid] = 0;
            if (tid == 0) g_ticket = 0;
        }
        int i = bid * 256 + tid;
        bool is64 = true;
        #pragma unroll
        for (int j = 0; j < 8; j++) {
            unsigned long long v = (unsigned long long)__ldg(&e[j * 7 + 1]);
            if (v >= (1ULL << 31)) is64 = false;
        }
        if (i < E) {
            int s, d;
            if (is64) { s = (int)e[i]; d = (int)e[E + i]; }
            else      { const int* p = (const int*)e; s = p[i]; d = p[E + i]; }
            g_src[i] = s; g_dst[i] = d;
            atomicAdd(&g_deg[d], 1);
        } else if (i < E + N) {
            int n = i - E;
            g_src[i] = n; g_dst[i] = n;
            atomicAdd(&g_deg[n], 1);
        }
        return;
    }
    // alpha blocks: per-warp GEMV of x against precomputed g_ws (4KB, L1-hot)
    int wid = tid >> 5, lane = tid & 31;
    int n = (bid - eblocks) * 8 + wid;
    if (n >= N) return;
    float4 xv = *(const float4*)&x[(size_t)n * 128 + lane * 4];
    float dot[8];
    #pragma unroll
    for (int v = 0; v < 8; v++) {
        float4 w = *(const float4*)&g_ws[v * 128 + lane * 4];
        dot[v] = xv.x * w.x + xv.y * w.y + xv.z * w.z + xv.w * w.w;
    }
    #pragma unroll
    for (int v = 0; v < 8; v++)
        #pragma unroll
        for (int o = 16; o; o >>= 1) dot[v] += __shfl_xor_sync(0xffffffffu, dot[v], o);
    if (lane == 0) {
        *(float4*)&g_alsrc[n * 4] = make_float4(dot[0], dot[2], dot[4], dot[6]);
        *(float4*)&g_aldst[n * 4] = make_float4(dot[1], dot[3], dot[5], dot[7]);
    }
}

// =============== 2. single-launch chained scan -> g_off, g_cur ===============
__global__ __launch_bounds__(1024) void k_scan(int n) {
    __shared__ int sh[1024];
    __shared__ int s_bid, s_excl;
    int tid = threadIdx.x;
    if (tid == 0) s_bid = atomicAdd(&g_ticket, 1);
    __syncthreads();
    int bid = s_bid;
    int i = bid * 1024 + tid;
    int d = (i < n) ? g_deg[i] : 0;
    sh[tid] = d;
    __syncthreads();
    #pragma unroll
    for (int o = 1; o < 1024; o <<= 1) {
        int t = (tid >= o) ? sh[tid - o] : 0;
        __syncthreads();
        sh[tid] += t;
        __syncthreads();
    }
    if (tid == 0) {
        int excl = 0;
        if (bid > 0) {
            while (g_bflag[bid - 1] != 2) { }
            __threadfence();
            excl = g_bval[bid - 1];
        }
        g_bval[bid] = excl + sh[1023];
        __threadfence();
        g_bflag[bid] = 2;
        s_excl = excl;
    }
    __syncthreads();
    int excl = s_excl;
    if (i < n) {
        int incl = sh[tid] + excl;
        g_off[i + 1] = incl;
        g_cur[i] = incl - d;
    }
    if (i == 0) g_off[0] = 0;
}

// =============== 3. scatter (+ deg reset) — PROFILED SLOT ====================
__global__ void k_scatter(int Etot, int N) {
    int i = blockIdx.x * blockDim.x + threadIdx.x;
    if (i < Etot) {
        int p = atomicAdd(&g_cur[g_dst[i]], 1);
        g_ssrc[p] = g_src[i];
    }
    if (i < N) g_deg[i] = 0;
}

// =============== 4. layer-1 aggregation over raw x ===========================
__global__ __launch_bounds__(256) void k_aggX(const float* __restrict__ x, int N) {
    int gw = (blockIdx.x * blockDim.x + threadIdx.x) >> 5;
    int lane = threadIdx.x & 31;
    if (gw >= N) return;
    int e0 = g_off[gw], e1 = g_off[gw + 1];
    float4 ald = *(const float4*)&g_aldst[gw * 4];
    float4 a0 = make_float4(0.f, 0.f, 0.f, 0.f), a1 = a0, a2 = a0, a3 = a0;
    float s0 = 0.f, s1 = 0.f, s2 = 0.f, s3 = 0.f;
    #pragma unroll 2
    for (int e = e0; e < e1; e++) {
        int sj = __ldg(&g_ssrc[e]);
        float4 as = *(const float4*)&g_alsrc[sj * 4];
        float w0 = __expf(lrelu(as.x + ald.x));
        float w1 = __expf(lrelu(as.y + ald.y));
        float w2 = __expf(lrelu(as.z + ald.z));
        float w3 = __expf(lrelu(as.w + ald.w));
        s0 += w0; s1 += w1; s2 += w2; s3 += w3;
        float4 v = __ldg((const float4*)&x[(size_t)sj * 128] + lane);
        a0.x += w0 * v.x; a0.y += w0 * v.y; a0.z += w0 * v.z; a0.w += w0 * v.w;
        a1.x += w1 * v.x; a1.y += w1 * v.y; a1.z += w1 * v.z; a1.w += w1 * v.w;
        a2.x += w2 * v.x; a2.y += w2 * v.y; a2.z += w2 * v.z; a2.w += w2 * v.w;
        a3.x += w3 * v.x; a3.y += w3 * v.y; a3.z += w3 * v.z; a3.w += w3 * v.w;
    }
    float i0 = 1.f / (s0 + 1e-16f), i1 = 1.f / (s1 + 1e-16f);
    float i2 = 1.f / (s2 + 1e-16f), i3 = 1.f / (s3 + 1e-16f);
    float4* Sp = (float4*)&g_S[(size_t)gw * 512];
    Sp[lane]      = make_float4(a0.x * i0, a0.y * i0, a0.z * i0, a0.w * i0);
    Sp[32 + lane] = make_float4(a1.x * i1, a1.y * i1, a1.z * i1, a1.w * i1);
    Sp[64 + lane] = make_float4(a2.x * i2, a2.y * i2, a2.z * i2, a2.w * i2);
    Sp[96 + lane] = make_float4(a3.x * i3, a3.y * i3, a3.z * i3, a3.w * i3);
}

// =============== 5. layer-1 post-GEMV (float4): g_act = S @ W1 + b1, ELU =====
// lane owns channels [4*lane, 4*lane+3] (head lane>>4) and [128+4*lane, ...]
__global__ __launch_bounds__(256) void k_postgemv(const float* __restrict__ W1,
                                                  const float* __restrict__ b1, int N) {
    int gw = (blockIdx.x * blockDim.x + threadIdx.x) >> 5;
    int lane = threadIdx.x & 31;
    if (gw >= N) return;
    const float* S = &g_S[(size_t)gw * 512];
    int hA = lane >> 4;        // head for channels 4*lane..4*lane+3   (0 or 1)
    int hB = hA + 2;           // head for channels 128+4*lane..+3     (2 or 3)
    float4 accA = make_float4(0.f, 0.f, 0.f, 0.f);
    float4 accB = make_float4(0.f, 0.f, 0.f, 0.f);
    #pragma unroll 4
    for (int k4 = 0; k4 < 128; k4 += 4) {
        float4 sA = *(const float4*)&S[hA * 128 + k4];
        float4 sB = *(const float4*)&S[hB * 128 + k4];
        #pragma unroll
        for (int j = 0; j < 4; j++) {
            float sa = j == 0 ? sA.x : j == 1 ? sA.y : j == 2 ? sA.z : sA.w;
            float sb = j == 0 ? sB.x : j == 1 ? sB.y : j == 2 ? sB.z : sB.w;
            const float* wr = &W1[(size_t)(k4 + j) * 256];
            float4 wA = __ldg((const float4*)&wr[4 * lane]);
            float4 wB = __ldg((const float4*)&wr[128 + 4 * lane]);
            accA.x += sa * wA.x; accA.y += sa * wA.y;
            accA.z += sa * wA.z; accA.w += sa * wA.w;
            accB.x += sb * wB.x; accB.y += sb * wB.y;
            accB.z += sb * wB.z; accB.w += sb * wB.w;
        }
    }
    float4 bA = __ldg((const float4*)&b1[4 * lane]);
    float4 bB = __ldg((const float4*)&b1[128 + 4 * lane]);
    float4 oA, oB;
    oA.x = accA.x + bA.x; oA.y = accA.y + bA.y;
    oA.z = accA.z + bA.z; oA.w = accA.w + bA.w;
    oB.x = accB.x + bB.x; oB.y = accB.y + bB.y;
    oB.z = accB.z + bB.z; oB.w = accB.w + bB.w;
    oA.x = oA.x > 0.f ? oA.x : (__expf(oA.x) - 1.f);
    oA.y = oA.y > 0.f ? oA.y : (__expf(oA.y) - 1.f);
    oA.z = oA.z > 0.f ? oA.z : (__expf(oA.z) - 1.f);
    oA.w = oA.w > 0.f ? oA.w : (__expf(oA.w) - 1.f);
    oB.x = oB.x > 0.f ? oB.x : (__expf(oB.x) - 1.f);
    oB.y = oB.y > 0.f ? oB.y : (__expf(oB.y) - 1.f);
    oB.z = oB.z > 0.f ? oB.z : (__expf(oB.z) - 1.f);
    oB.w = oB.w > 0.f ? oB.w : (__expf(oB.w) - 1.f);
    *(float4*)&g_act[(size_t)gw * 256 + 4 * lane] = oA;
    *(float4*)&g_act[(size_t)gw * 256 + 128 + 4 * lane] = oB;
}

// =============== 6. layer-2 GEMV (float4): g_feat = g_act @ W2 ===============
__global__ __launch_bounds__(256) void k_gemv2(const float* __restrict__ W2, int N) {
    int gw = (blockIdx.x * blockDim.x + threadIdx.x) >> 5;
    int lane = threadIdx.x & 31;
    if (gw >= N) return;
    const float* arow = &g_act[(size_t)gw * 256];
    float4 acc0 = make_float4(0.f, 0.f, 0.f, 0.f);
    float4 acc1 = make_float4(0.f, 0.f, 0.f, 0.f);
    #pragma unroll 2
    for (int k4 = 0; k4 < 256; k4 += 4) {
        float4 a4 = *(const float4*)&arow[k4];      // broadcast
        #pragma unroll
        for (int j = 0; j < 4; j++) {
            float a = j == 0 ? a4.x : j == 1 ? a4.y : j == 2 ? a4.z : a4.w;
            const float* wr = &W2[(size_t)(k4 + j) * 256];
            float4 w0 = __ldg((const float4*)&wr[4 * lane]);
            float4 w1 = __ldg((const float4*)&wr[128 + 4 * lane]);
            acc0.x += a * w0.x; acc0.y += a * w0.y;
            acc0.z += a * w0.z; acc0.w += a * w0.w;
            acc1.x += a * w1.x; acc1.y += a * w1.y;
            acc1.z += a * w1.z; acc1.w += a * w1.w;
        }
    }
    *(float4*)&g_feat[(size_t)gw * 256 + 4 * lane] = acc0;
    *(float4*)&g_feat[(size_t)gw * 256 + 128 + 4 * lane] = acc1;
}

// =============== 7. layer-2 alphas (reads g_feat internally) =================
__global__ void k_alphas(const float* __restrict__ asrc,
                         const float* __restrict__ adst, int N) {
    int warp = (blockIdx.x * blockDim.x + threadIdx.x) >> 5;
    int lane = threadIdx.x & 31;
    if (warp >= N) return;
    const float4* row = (const float4*)&g_feat[(size_t)warp * FDIM];
    const float4* as4 = (const float4*)asrc;
    const float4* ad4 = (const float4*)adst;
    float4 va = row[lane];        // heads 0|1 split at lane 16
    float4 vb = row[32 + lane];   // heads 2|3
    float4 wa = __ldg(&as4[lane]),      wb = __ldg(&as4[32 + lane]);
    float4 da = __ldg(&ad4[lane]),      db = __ldg(&ad4[32 + lane]);
    float pa = va.x * wa.x + va.y * wa.y + va.z * wa.z + va.w * wa.w;
    float pb = vb.x * wb.x + vb.y * wb.y + vb.z * wb.z + vb.w * wb.w;
    float qa = va.x * da.x + va.y * da.y + va.z * da.z + va.w * da.w;
    float qb = vb.x * db.x + vb.y * db.y + vb.z * db.z + vb.w * db.w;
    #pragma unroll
    for (int o = 8; o; o >>= 1) {
        pa += __shfl_xor_sync(0xffffffffu, pa, o);
        pb += __shfl_xor_sync(0xffffffffu, pb, o);
        qa += __shfl_xor_sync(0xffffffffu, qa, o);
        qb += __shfl_xor_sync(0xffffffffu, qb, o);
    }
    if (lane == 0)  { g_alsrc[warp * 4 + 0] = pa; g_alsrc[warp * 4 + 2] = pb;
                      g_aldst[warp * 4 + 0] = qa; g_aldst[warp * 4 + 2] = qb; }
    if (lane == 16) { g_alsrc[warp * 4 + 1] = pa; g_alsrc[warp * 4 + 3] = pb;
                      g_aldst[warp * 4 + 1] = qa; g_aldst[warp * 4 + 3] = qb; }
}

// =============== 8. layer-2 aggregation (2 warps/node, writes g_act) =========
__global__ __launch_bounds__(256) void k_aggregate(const float* __restrict__ bias, int N) {
    int gw = (blockIdx.x * blockDim.x + threadIdx.x) >> 5;
    int lane = threadIdx.x & 31;
    int n = gw >> 1, half = gw & 1;
    if (n >= N) return;
    int e0 = g_off[n], e1 = g_off[n + 1];
    float2 ald = *(const float2*)&g_aldst[n * 4 + half * 2];
    bool lo = lane < 16;

    float4 acc = make_float4(0.f, 0.f, 0.f, 0.f);
    float sE = 0.f, sO = 0.f;
    #pragma unroll 4
    for (int e = e0; e < e1; e++) {
        int sj = __ldg(&g_ssrc[e]);
        float2 as = *(const float2*)&g_alsrc[sj * 4 + half * 2];
        float we = __expf(lrelu(as.x + ald.x));
        float wo = __expf(lrelu(as.y + ald.y));
        sE += we; sO += wo;
        float4 v = __ldg((const float4*)&g_feat[(size_t)sj * FDIM + half * 128] + lane);
        float w = lo ? we : wo;
        acc.x += w * v.x; acc.y += w * v.y; acc.z += w * v.z; acc.w += w * v.w;
    }
    float inv = 1.f / ((lo ? sE : sO) + 1e-16f);
    float4 b = __ldg((const float4*)&bias[half * 128] + lane);
    float4 o;
    o.x = acc.x * inv + b.x; o.y = acc.y * inv + b.y;
    o.z = acc.z * inv + b.z; o.w = acc.w * inv + b.w;
    o.x = o.x > 0.f ? o.x : (__expf(o.x) - 1.f);
    o.y = o.y > 0.f ? o.y : (__expf(o.y) - 1.f);
    o.z = o.z > 0.f ? o.z : (__expf(o.z) - 1.f);
    o.w = o.w > 0.f ? o.w : (__expf(o.w) - 1.f);
    *((float4*)&g_act[(size_t)n * FDIM + half * 128] + lane) = o;
}

// =============== 9. W3 GEMV (reads g_act internally) =========================
__global__ void k_dotw3(const float* __restrict__ W3, int N) {
    int warp = (blockIdx.x * blockDim.x + threadIdx.x) >> 5;
    int lane = threadIdx.x & 31;
    if (warp >= N) return;
    const float4* row = (const float4*)&g_act[(size_t)warp * FDIM];
    const float4* w = (const float4*)W3;
    float4 a = row[lane], b = __ldg(&w[lane]);
    float4 a2 = row[32 + lane], b2 = __ldg(&w[32 + lane]);
    float p = a.x * b.x + a.y * b.y + a.z * b.z + a.w * b.w
            + a2.x * b2.x + a2.y * b2.y + a2.z * b2.z + a2.w * b2.w;
    #pragma unroll
    for (int o = 16; o; o >>= 1) p += __shfl_xor_sync(0xffffffffu, p, o);
    if (lane == 0) g_h3[warp] = p;
}

// =============== 10. layer-3 aggregation -> d_out ============================
__global__ void k_agg3(const float* __restrict__ asrc3, const float* __restrict__ adst3,
                       const float* __restrict__ b3, float* __restrict__ out, int N) {
    int n = blockIdx.x * blockDim.x + threadIdx.x;
    if (n >= N) return;
    float as = __ldg(&asrc3[0]);
    float hd = g_h3[n] * __ldg(&adst3[0]);
    int e0 = g_off[n], e1 = g_off[n + 1];
    float num = 0.f, den = 0.f;
    #pragma unroll 4
    for (int e = e0; e < e1; e++) {
        float hs = g_h3[__ldg(&g_ssrc[e])];
        float w = __expf(lrelu(hs * as + hd));
        num += w * hs;
        den += w;
    }
    out[n] = num / (den + 1e-16f) + __ldg(&b3[0]);
}

// ---------------- launch: ONLY harness pointers cross the boundary ----------
extern "C" void kernel_launch(void* const* d_in, const int* in_sizes, int n_in,
                              void* d_out, int out_size) {
    const float* x      = (const float*)d_in[0];
    const void*  eidx   = d_in[1];
    const float* W1     = (const float*)d_in[2];
    const float* asrc1  = (const float*)d_in[3];
    const float* adst1  = (const float*)d_in[4];
    const float* b1     = (const float*)d_in[5];
    const float* W2     = (const float*)d_in[6];
    const float* asrc2  = (const float*)d_in[7];
    const float* adst2  = (const float*)d_in[8];
    const float* b2     = (const float*)d_in[9];
    const float* W3     = (const float*)d_in[10];
    const float* asrc3  = (const float*)d_in[11];
    const float* adst3  = (const float*)d_in[12];
    const float* b3     = (const float*)d_in[13];
    float* out = (float*)d_out;

    int N = in_sizes[0] / 128;        // 50000
    int E = in_sizes[1] / 2;          // 650000
    int Etot = E + N;
    int nb = (N + 1023) / 1024;

    int eblocks = (Etot + 255) / 256;
    int ablocks = (N + 7) / 8;
    int wblocks  = (N + 7) / 8;            // warp per node
    int wblocks2 = (2 * N + 7) / 8;        // 2 warps per node

    k_ws<<<1, 256>>>(W1, asrc1, adst1);                                     // 1
    k_prep<<<eblocks + ablocks, 256>>>((const long long*)eidx, E, N, x,
                                       eblocks);                            // 2
    k_scan<<<nb, 1024>>>(N);                                                // 3
    k_scatter<<<eblocks, 256>>>(Etot, N);                                   // 4 (profiled)
    k_aggX<<<wblocks, 256>>>(x, N);                                         // 5
    k_postgemv<<<wblocks, 256>>>(W1, b1, N);                                // 6
    k_gemv2<<<wblocks, 256>>>(W2, N);                                       // 7
    k_alphas<<<wblocks, 256>>>(asrc2, adst2, N);                            // 8
    k_aggregate<<<wblocks2, 256>>>(b2, N);                                  // 9
    k_dotw3<<<wblocks, 256>>>(W3, N);                                       // 10
    k_agg3<<<(N + 255) / 256, 256>>>(asrc3, adst3, b3, out, N);             // 11

    (void)n_in; (void)out_size;
}

// round 16
// speedup vs baseline: 19.1276x; 1.6807x over previous
#include <cuda_runtime.h>
#include <math.h>
#include <stdint.h>

#define NMAX   50000
#define EMAX   700000     // 650000 edges + 50000 self loops
#define FDIM   256
#define HEADS  4
#define NEG_SLOPE 0.2f

// ------- scratch: device globals, ONLY ever accessed inside kernels ---------
// (NEVER pass these as kernel args: host-side shadow + ATS = silent host-mem
//  traffic and split-brain buffers — the R8-R12 root cause)
__device__ int   g_src [EMAX];
__device__ int   g_dst [EMAX];
__device__ int   g_ssrc[EMAX];
__device__ int   g_deg [NMAX];
__device__ int   g_off [NMAX + 1];
__device__ int   g_cur [NMAX];
__device__ int   g_ticket;
__device__ volatile int g_bflag[64];
__device__ int   g_bval[64];
__device__ __align__(16) float g_ws  [8 * 128];      // W1-projected alpha vectors
__device__ __align__(16) float g_S   [NMAX * 512];   // layer-1 weighted-x sums
__device__ __align__(16) float g_feat[NMAX * FDIM];  // layer-2 h (pre-attention)
__device__ __align__(16) float g_act [NMAX * FDIM];  // layer-1 activations
__device__ __align__(16) float g_alsrc[NMAX * HEADS];
__device__ __align__(16) float g_aldst[NMAX * HEADS];
__device__ float g_h3  [NMAX];

__device__ __forceinline__ float lrelu(float x) { return x > 0.f ? x : NEG_SLOPE * x; }
__device__ __forceinline__ uint32_t f2tf(float f) {
    uint32_t r;
    asm("cvt.rna.tf32.f32 %0, %1;" : "=r"(r) : "f"(f));
    return r;
}
__device__ __forceinline__ void mma_tf32(float* d, const uint32_t* a, const uint32_t* b) {
    asm volatile(
        "mma.sync.aligned.m16n8k8.row.col.f32.tf32.tf32.f32 "
        "{%0,%1,%2,%3}, {%4,%5,%6,%7}, {%8,%9}, {%0,%1,%2,%3};"
        : "+f"(d[0]), "+f"(d[1]), "+f"(d[2]), "+f"(d[3])
        : "r"(a[0]), "r"(a[1]), "r"(a[2]), "r"(a[3]), "r"(b[0]), "r"(b[1]));
}
__device__ __forceinline__ void cp16z(uint32_t s, const void* g, int sz) {
    asm volatile("cp.async.cg.shared.global [%0], [%1], 16, %2;"
                 :: "r"(s), "l"(g), "r"(sz));
}
__device__ __forceinline__ void cp_commit() { asm volatile("cp.async.commit_group;"); }
__device__ __forceinline__ void cp_wait1()  { asm volatile("cp.async.wait_group 1;"); }

// =============== 0. ws projection (one block): g_ws[v][k] ====================
__global__ void k_ws(const float* __restrict__ W1,
                     const float* __restrict__ asrc,
                     const float* __restrict__ adst) {
    int wid = threadIdx.x >> 5, lane = threadIdx.x & 31;
    int v = wid, head = v >> 1;
    const float* avec = (v & 1) ? adst : asrc;
    float a0 = __ldg(&avec[head * 64 + lane]);
    float a1 = __ldg(&avec[head * 64 + 32 + lane]);
    for (int k = 0; k < 128; k++) {
        float s = __ldg(&W1[k * 256 + head * 64 + lane]) * a0
                + __ldg(&W1[k * 256 + head * 64 + 32 + lane]) * a1;
        #pragma unroll
        for (int o = 16; o; o >>= 1) s += __shfl_xor_sync(0xffffffffu, s, o);
        if (lane == 0) g_ws[v * 128 + k] = s;
    }
}

// =============== 1. prep: edge build+hist  ||  layer-1 alphas from x =========
__global__ __launch_bounds__(256) void k_prep(const long long* __restrict__ e, int E, int N,
                                              const float* __restrict__ x, int eblocks) {
    int bid = blockIdx.x, tid = threadIdx.x;
    if (bid < eblocks) {
        if (bid == 0 && tid < 64) {                   // reset scan state per replay
            g_bflag[tid] = 0;
            if (tid == 0) g_ticket = 0;
        }
        int i = bid * 256 + tid;
        bool is64 = true;
        #pragma unroll
        for (int j = 0; j < 8; j++) {
            unsigned long long v = (unsigned long long)__ldg(&e[j * 7 + 1]);
            if (v >= (1ULL << 31)) is64 = false;
        }
        if (i < E) {
            int s, d;
            if (is64) { s = (int)e[i]; d = (int)e[E + i]; }
            else      { const int* p = (const int*)e; s = p[i]; d = p[E + i]; }
            g_src[i] = s; g_dst[i] = d;
            atomicAdd(&g_deg[d], 1);
        } else if (i < E + N) {
            int n = i - E;
            g_src[i] = n; g_dst[i] = n;
            atomicAdd(&g_deg[n], 1);
        }
        return;
    }
    int wid = tid >> 5, lane = tid & 31;
    int n = (bid - eblocks) * 8 + wid;
    if (n >= N) return;
    float4 xv = *(const float4*)&x[(size_t)n * 128 + lane * 4];
    float dot[8];
    #pragma unroll
    for (int v = 0; v < 8; v++) {
        float4 w = *(const float4*)&g_ws[v * 128 + lane * 4];
        dot[v] = xv.x * w.x + xv.y * w.y + xv.z * w.z + xv.w * w.w;
    }
    #pragma unroll
    for (int v = 0; v < 8; v++)
        #pragma unroll
        for (int o = 16; o; o >>= 1) dot[v] += __shfl_xor_sync(0xffffffffu, dot[v], o);
    if (lane == 0) {
        *(float4*)&g_alsrc[n * 4] = make_float4(dot[0], dot[2], dot[4], dot[6]);
        *(float4*)&g_aldst[n * 4] = make_float4(dot[1], dot[3], dot[5], dot[7]);
    }
}

// =============== 2. single-launch chained scan -> g_off, g_cur ===============
__global__ __launch_bounds__(1024) void k_scan(int n) {
    __shared__ int sh[1024];
    __shared__ int s_bid, s_excl;
    int tid = threadIdx.x;
    if (tid == 0) s_bid = atomicAdd(&g_ticket, 1);
    __syncthreads();
    int bid = s_bid;
    int i = bid * 1024 + tid;
    int d = (i < n) ? g_deg[i] : 0;
    sh[tid] = d;
    __syncthreads();
    #pragma unroll
    for (int o = 1; o < 1024; o <<= 1) {
        int t = (tid >= o) ? sh[tid - o] : 0;
        __syncthreads();
        sh[tid] += t;
        __syncthreads();
    }
    if (tid == 0) {
        int excl = 0;
        if (bid > 0) {
            while (g_bflag[bid - 1] != 2) { }
            __threadfence();
            excl = g_bval[bid - 1];
        }
        g_bval[bid] = excl + sh[1023];
        __threadfence();
        g_bflag[bid] = 2;
        s_excl = excl;
    }
    __syncthreads();
    int excl = s_excl;
    if (i < n) {
        int incl = sh[tid] + excl;
        g_off[i + 1] = incl;
        g_cur[i] = incl - d;
    }
    if (i == 0) g_off[0] = 0;
}

// =============== 3. scatter (+ deg reset) — PROFILED SLOT ====================
__global__ void k_scatter(int Etot, int N) {
    int i = blockIdx.x * blockDim.x + threadIdx.x;
    if (i < Etot) {
        int p = atomicAdd(&g_cur[g_dst[i]], 1);
        g_ssrc[p] = g_src[i];
    }
    if (i < N) g_deg[i] = 0;
}

// =============== 4. layer-1 aggregation over raw x ===========================
__global__ __launch_bounds__(256) void k_aggX(const float* __restrict__ x, int N) {
    int gw = (blockIdx.x * blockDim.x + threadIdx.x) >> 5;
    int lane = threadIdx.x & 31;
    if (gw >= N) return;
    int e0 = g_off[gw], e1 = g_off[gw + 1];
    float4 ald = *(const float4*)&g_aldst[gw * 4];
    float4 a0 = make_float4(0.f, 0.f, 0.f, 0.f), a1 = a0, a2 = a0, a3 = a0;
    float s0 = 0.f, s1 = 0.f, s2 = 0.f, s3 = 0.f;
    #pragma unroll 2
    for (int e = e0; e < e1; e++) {
        int sj = __ldg(&g_ssrc[e]);
        float4 as = *(const float4*)&g_alsrc[sj * 4];
        float w0 = __expf(lrelu(as.x + ald.x));
        float w1 = __expf(lrelu(as.y + ald.y));
        float w2 = __expf(lrelu(as.z + ald.z));
        float w3 = __expf(lrelu(as.w + ald.w));
        s0 += w0; s1 += w1; s2 += w2; s3 += w3;
        float4 v = __ldg((const float4*)&x[(size_t)sj * 128] + lane);
        a0.x += w0 * v.x; a0.y += w0 * v.y; a0.z += w0 * v.z; a0.w += w0 * v.w;
        a1.x += w1 * v.x; a1.y += w1 * v.y; a1.z += w1 * v.z; a1.w += w1 * v.w;
        a2.x += w2 * v.x; a2.y += w2 * v.y; a2.z += w2 * v.z; a2.w += w2 * v.w;
        a3.x += w3 * v.x; a3.y += w3 * v.y; a3.z += w3 * v.z; a3.w += w3 * v.w;
    }
    float i0 = 1.f / (s0 + 1e-16f), i1 = 1.f / (s1 + 1e-16f);
    float i2 = 1.f / (s2 + 1e-16f), i3 = 1.f / (s3 + 1e-16f);
    float4* Sp = (float4*)&g_S[(size_t)gw * 512];
    Sp[lane]      = make_float4(a0.x * i0, a0.y * i0, a0.z * i0, a0.w * i0);
    Sp[32 + lane] = make_float4(a1.x * i1, a1.y * i1, a1.z * i1, a1.w * i1);
    Sp[64 + lane] = make_float4(a2.x * i2, a2.y * i2, a2.z * i2, a2.w * i2);
    Sp[96 + lane] = make_float4(a3.x * i3, a3.y * i3, a3.z * i3, a3.w * i3);
}

// =============== 5. layer-1 post-GEMV (float4): g_act = S @ W1 + b1, ELU =====
__global__ __launch_bounds__(256) void k_postgemv(const float* __restrict__ W1,
                                                  const float* __restrict__ b1, int N) {
    int gw = (blockIdx.x * blockDim.x + threadIdx.x) >> 5;
    int lane = threadIdx.x & 31;
    if (gw >= N) return;
    const float* S = &g_S[(size_t)gw * 512];
    int hA = lane >> 4;
    int hB = hA + 2;
    float4 accA = make_float4(0.f, 0.f, 0.f, 0.f);
    float4 accB = make_float4(0.f, 0.f, 0.f, 0.f);
    #pragma unroll 4
    for (int k4 = 0; k4 < 128; k4 += 4) {
        float4 sA = *(const float4*)&S[hA * 128 + k4];
        float4 sB = *(const float4*)&S[hB * 128 + k4];
        #pragma unroll
        for (int j = 0; j < 4; j++) {
            float sa = j == 0 ? sA.x : j == 1 ? sA.y : j == 2 ? sA.z : sA.w;
            float sb = j == 0 ? sB.x : j == 1 ? sB.y : j == 2 ? sB.z : sB.w;
            const float* wr = &W1[(size_t)(k4 + j) * 256];
            float4 wA = __ldg((const float4*)&wr[4 * lane]);
            float4 wB = __ldg((const float4*)&wr[128 + 4 * lane]);
            accA.x += sa * wA.x; accA.y += sa * wA.y;
            accA.z += sa * wA.z; accA.w += sa * wA.w;
            accB.x += sb * wB.x; accB.y += sb * wB.y;
            accB.z += sb * wB.z; accB.w += sb * wB.w;
        }
    }
    float4 bA = __ldg((const float4*)&b1[4 * lane]);
    float4 bB = __ldg((const float4*)&b1[128 + 4 * lane]);
    float4 oA, oB;
    oA.x = accA.x + bA.x; oA.y = accA.y + bA.y;
    oA.z = accA.z + bA.z; oA.w = accA.w + bA.w;
    oB.x = accB.x + bB.x; oB.y = accB.y + bB.y;
    oB.z = accB.z + bB.z; oB.w = accB.w + bB.w;
    oA.x = oA.x > 0.f ? oA.x : (__expf(oA.x) - 1.f);
    oA.y = oA.y > 0.f ? oA.y : (__expf(oA.y) - 1.f);
    oA.z = oA.z > 0.f ? oA.z : (__expf(oA.z) - 1.f);
    oA.w = oA.w > 0.f ? oA.w : (__expf(oA.w) - 1.f);
    oB.x = oB.x > 0.f ? oB.x : (__expf(oB.x) - 1.f);
    oB.y = oB.y > 0.f ? oB.y : (__expf(oB.y) - 1.f);
    oB.z = oB.z > 0.f ? oB.z : (__expf(oB.z) - 1.f);
    oB.w = oB.w > 0.f ? oB.w : (__expf(oB.w) - 1.f);
    *(float4*)&g_act[(size_t)gw * 256 + 4 * lane] = oA;
    *(float4*)&g_act[(size_t)gw * 256 + 128 + 4 * lane] = oB;
}

// =============== 6. layer-2 GEMM (tf32 MMA, cp.async): g_feat = g_act @ W2 ===
// BM=128 BN=128 BK=16, 256 threads, warp tile 32x64. A internal, C internal.
__global__ __launch_bounds__(256) void k_gemm2(const float* __restrict__ B, int M) {
    __shared__ float As[2][128][20];
    __shared__ float Bs[2][16][136];
    const float* A = g_act;                     // internal device global
    int tid = threadIdx.x;
    int lane = tid & 31, wid = tid >> 5;
    int gid = lane >> 2, tig = lane & 3;
    int warp_m = wid >> 1, warp_n = wid & 1;
    int brow = blockIdx.y * 128, bcol = blockIdx.x * 128;

    int ar0 = tid >> 2,          ak0 = (tid & 3) << 2;
    int ar1 = (tid + 256) >> 2,  ak1 = ((tid + 256) & 3) << 2;
    int bk0 = tid >> 5,          bn0 = (tid & 31) << 2;
    int bk1 = (tid + 256) >> 5,  bn1 = ((tid + 256) & 31) << 2;
    bool av0 = (brow + ar0) < M, av1 = (brow + ar1) < M;
    const float* Ar0 = A + (size_t)(av0 ? brow + ar0 : 0) * FDIM + ak0;
    const float* Ar1 = A + (size_t)(av1 ? brow + ar1 : 0) * FDIM + ak1;
    const float* Br0 = B + (size_t)bk0 * FDIM + bcol + bn0;
    const float* Br1 = B + (size_t)bk1 * FDIM + bcol + bn1;

    uint32_t sa0[2], sa1[2], sb0[2], sb1[2];
    #pragma unroll
    for (int s = 0; s < 2; s++) {
        sa0[s] = (uint32_t)__cvta_generic_to_shared(&As[s][ar0][ak0]);
        sa1[s] = (uint32_t)__cvta_generic_to_shared(&As[s][ar1][ak1]);
        sb0[s] = (uint32_t)__cvta_generic_to_shared(&Bs[s][bk0][bn0]);
        sb1[s] = (uint32_t)__cvta_generic_to_shared(&Bs[s][bk1][bn1]);
    }

    float acc[2][8][4];
    #pragma unroll
    for (int mt = 0; mt < 2; mt++)
        #pragma unroll
        for (int nt = 0; nt < 8; nt++)
            #pragma unroll
            for (int q = 0; q < 4; q++) acc[mt][nt][q] = 0.f;

    const int ntile = FDIM >> 4;               // 16
    cp16z(sa0[0], Ar0, av0 ? 16 : 0);
    cp16z(sa1[0], Ar1, av1 ? 16 : 0);
    cp16z(sb0[0], Br0, 16);
    cp16z(sb1[0], Br1, 16);
    cp_commit();

    for (int t = 0; t < ntile; t++) {
        int nxt = t + 1;
        if (nxt < ntile) {
            int slot = nxt & 1;
            cp16z(sa0[slot], Ar0 + nxt * 16, av0 ? 16 : 0);
            cp16z(sa1[slot], Ar1 + nxt * 16, av1 ? 16 : 0);
            cp16z(sb0[slot], Br0 + (size_t)nxt * 16 * FDIM, 16);
            cp16z(sb1[slot], Br1 + (size_t)nxt * 16 * FDIM, 16);
        }
        cp_commit();
        cp_wait1();
        __syncthreads();
        int cur = t & 1;
        #pragma unroll
        for (int k8 = 0; k8 < 2; k8++) {
            int kb = k8 * 8;
            uint32_t af[2][4];
            #pragma unroll
            for (int mt = 0; mt < 2; mt++) {
                int mb = warp_m * 32 + mt * 16 + gid;
                af[mt][0] = f2tf(As[cur][mb    ][kb + tig]);
                af[mt][1] = f2tf(As[cur][mb + 8][kb + tig]);
                af[mt][2] = f2tf(As[cur][mb    ][kb + tig + 4]);
                af[mt][3] = f2tf(As[cur][mb + 8][kb + tig + 4]);
            }
            uint32_t bf[8][2];
            #pragma unroll
            for (int nt = 0; nt < 8; nt++) {
                int nb = warp_n * 64 + nt * 8 + gid;
                bf[nt][0] = f2tf(Bs[cur][kb + tig    ][nb]);
                bf[nt][1] = f2tf(Bs[cur][kb + tig + 4][nb]);
            }
            #pragma unroll
            for (int mt = 0; mt < 2; mt++)
                #pragma unroll
                for (int nt = 0; nt < 8; nt++)
                    mma_tf32(acc[mt][nt], af[mt], bf[nt]);
        }
        __syncthreads();
    }
    #pragma unroll
    for (int mt = 0; mt < 2; mt++) {
        int r0 = brow + warp_m * 32 + mt * 16 + gid;
        #pragma unroll
        for (int nt = 0; nt < 8; nt++) {
            int c = bcol + warp_n * 64 + nt * 8 + 2 * tig;
            if (r0 < M)
                *(float2*)&g_feat[(size_t)r0 * FDIM + c] = make_float2(acc[mt][nt][0], acc[mt][nt][1]);
            if (r0 + 8 < M)
                *(float2*)&g_feat[(size_t)(r0 + 8) * FDIM + c] = make_float2(acc[mt][nt][2], acc[mt][nt][3]);
        }
    }
}

// =============== 7. layer-2 alphas (reads g_feat internally) =================
__global__ void k_alphas(const float* __restrict__ asrc,
                         const float* __restrict__ adst, int N) {
    int warp = (blockIdx.x * blockDim.x + threadIdx.x) >> 5;
    int lane = threadIdx.x & 31;
    if (warp >= N) return;
    const float4* row = (const float4*)&g_feat[(size_t)warp * FDIM];
    const float4* as4 = (const float4*)asrc;
    const float4* ad4 = (const float4*)adst;
    float4 va = row[lane];        // heads 0|1 split at lane 16
    float4 vb = row[32 + lane];   // heads 2|3
    float4 wa = __ldg(&as4[lane]),      wb = __ldg(&as4[32 + lane]);
    float4 da = __ldg(&ad4[lane]),      db = __ldg(&ad4[32 + lane]);
    float pa = va.x * wa.x + va.y * wa.y + va.z * wa.z + va.w * wa.w;
    float pb = vb.x * wb.x + vb.y * wb.y + vb.z * wb.z + vb.w * wb.w;
    float qa = va.x * da.x + va.y * da.y + va.z * da.z + va.w * da.w;
    float qb = vb.x * db.x + vb.y * db.y + vb.z * db.z + vb.w * db.w;
    #pragma unroll
    for (int o = 8; o; o >>= 1) {
        pa += __shfl_xor_sync(0xffffffffu, pa, o);
        pb += __shfl_xor_sync(0xffffffffu, pb, o);
        qa += __shfl_xor_sync(0xffffffffu, qa, o);
        qb += __shfl_xor_sync(0xffffffffu, qb, o);
    }
    if (lane == 0)  { g_alsrc[warp * 4 + 0] = pa; g_alsrc[warp * 4 + 2] = pb;
                      g_aldst[warp * 4 + 0] = qa; g_aldst[warp * 4 + 2] = qb; }
    if (lane == 16) { g_alsrc[warp * 4 + 1] = pa; g_alsrc[warp * 4 + 3] = pb;
                      g_aldst[warp * 4 + 1] = qa; g_aldst[warp * 4 + 3] = qb; }
}

// =============== 8. layer-2 aggregation + bias + ELU + W3-dot (fused) ========
// warp per node. Lane owns float4 groups: A = channels [4*lane..+3] (head lane>>4),
// B = channels [128+4*lane..+3] (head 2+(lane>>4)). Output consumed in-register.
__global__ __launch_bounds__(256) void k_agg2f(const float* __restrict__ bias,
                                               const float* __restrict__ W3, int N) {
    int gw = (blockIdx.x * blockDim.x + threadIdx.x) >> 5;
    int lane = threadIdx.x & 31;
    if (gw >= N) return;
    int e0 = g_off[gw], e1 = g_off[gw + 1];
    float4 ald = *(const float4*)&g_aldst[gw * 4];
    bool lo = lane < 16;
    float4 accA = make_float4(0.f, 0.f, 0.f, 0.f);
    float4 accB = make_float4(0.f, 0.f, 0.f, 0.f);
    float s0 = 0.f, s1 = 0.f, s2 = 0.f, s3 = 0.f;
    #pragma unroll 2
    for (int e = e0; e < e1; e++) {
        int sj = __ldg(&g_ssrc[e]);
        float4 as = *(const float4*)&g_alsrc[sj * 4];
        float w0 = __expf(lrelu(as.x + ald.x));
        float w1 = __expf(lrelu(as.y + ald.y));
        float w2 = __expf(lrelu(as.z + ald.z));
        float w3 = __expf(lrelu(as.w + ald.w));
        s0 += w0; s1 += w1; s2 += w2; s3 += w3;
        const float4* hp = (const float4*)&g_feat[(size_t)sj * FDIM];
        float4 vA = __ldg(hp + lane);
        float4 vB = __ldg(hp + 32 + lane);
        float wA = lo ? w0 : w1;
        float wB = lo ? w2 : w3;
        accA.x += wA * vA.x; accA.y += wA * vA.y; accA.z += wA * vA.z; accA.w += wA * vA.w;
        accB.x += wB * vB.x; accB.y += wB * vB.y; accB.z += wB * vB.z; accB.w += wB * vB.w;
    }
    float invA = 1.f / ((lo ? s0 : s1) + 1e-16f);
    float invB = 1.f / ((lo ? s2 : s3) + 1e-16f);
    float4 bA = __ldg((const float4*)bias + lane);
    float4 bB = __ldg((const float4*)bias + 32 + lane);
    float4 oA, oB;
    oA.x = accA.x * invA + bA.x; oA.y = accA.y * invA + bA.y;
    oA.z = accA.z * invA + bA.z; oA.w = accA.w * invA + bA.w;
    oB.x = accB.x * invB + bB.x; oB.y = accB.y * invB + bB.y;
    oB.z = accB.z * invB + bB.z; oB.w = accB.w * invB + bB.w;
    oA.x = oA.x > 0.f ? oA.x : (__expf(oA.x) - 1.f);
    oA.y = oA.y > 0.f ? oA.y : (__expf(oA.y) - 1.f);
    oA.z = oA.z > 0.f ? oA.z : (__expf(oA.z) - 1.f);
    oA.w = oA.w > 0.f ? oA.w : (__expf(oA.w) - 1.f);
    oB.x = oB.x > 0.f ? oB.x : (__expf(oB.x) - 1.f);
    oB.y = oB.y > 0.f ? oB.y : (__expf(oB.y) - 1.f);
    oB.z = oB.z > 0.f ? oB.z : (__expf(oB.z) - 1.f);
    oB.w = oB.w > 0.f ? oB.w : (__expf(oB.w) - 1.f);
    float4 wA4 = __ldg((const float4*)W3 + lane);
    float4 wB4 = __ldg((const float4*)W3 + 32 + lane);
    float p = oA.x * wA4.x + oA.y * wA4.y + oA.z * wA4.z + oA.w * wA4.w
            + oB.x * wB4.x + oB.y * wB4.y + oB.z * wB4.z + oB.w * wB4.w;
    #pragma unroll
    for (int o = 16; o; o >>= 1) p += __shfl_xor_sync(0xffffffffu, p, o);
    if (lane == 0) g_h3[gw] = p;
}

// =============== 9. layer-3 aggregation -> d_out =============================
__global__ void k_agg3(const float* __restrict__ asrc3, const float* __restrict__ adst3,
                       const float* __restrict__ b3, float* __restrict__ out, int N) {
    int n = blockIdx.x * blockDim.x + threadIdx.x;
    if (n >= N) return;
    float as = __ldg(&asrc3[0]);
    float hd = g_h3[n] * __ldg(&adst3[0]);
    int e0 = g_off[n], e1 = g_off[n + 1];
    float num = 0.f, den = 0.f;
    #pragma unroll 4
    for (int e = e0; e < e1; e++) {
        float hs = g_h3[__ldg(&g_ssrc[e])];
        float w = __expf(lrelu(hs * as + hd));
        num += w * hs;
        den += w;
    }
    out[n] = num / (den + 1e-16f) + __ldg(&b3[0]);
}

// ---------------- launch: ONLY harness pointers cross the boundary ----------
extern "C" void kernel_launch(void* const* d_in, const int* in_sizes, int n_in,
                              void* d_out, int out_size) {
    const float* x      = (const float*)d_in[0];
    const void*  eidx   = d_in[1];
    const float* W1     = (const float*)d_in[2];
    const float* asrc1  = (const float*)d_in[3];
    const float* adst1  = (const float*)d_in[4];
    const float* b1     = (const float*)d_in[5];
    const float* W2     = (const float*)d_in[6];
    const float* asrc2  = (const float*)d_in[7];
    const float* adst2  = (const float*)d_in[8];
    const float* b2     = (const float*)d_in[9];
    const float* W3     = (const float*)d_in[10];
    const float* asrc3  = (const float*)d_in[11];
    const float* adst3  = (const float*)d_in[12];
    const float* b3     = (const float*)d_in[13];
    float* out = (float*)d_out;

    int N = in_sizes[0] / 128;        // 50000
    int E = in_sizes[1] / 2;          // 650000
    int Etot = E + N;
    int nb = (N + 1023) / 1024;

    int eblocks = (Etot + 255) / 256;
    int ablocks = (N + 7) / 8;
    int wblocks = (N + 7) / 8;
    dim3 ggrid(FDIM / 128, (N + 127) / 128);

    k_ws<<<1, 256>>>(W1, asrc1, adst1);                                     // 1
    k_prep<<<eblocks + ablocks, 256>>>((const long long*)eidx, E, N, x,
                                       eblocks);                            // 2
    k_scan<<<nb, 1024>>>(N);                                                // 3
    k_scatter<<<eblocks, 256>>>(Etot, N);                                   // 4 (profiled)
    k_aggX<<<wblocks, 256>>>(x, N);                                         // 5
    k_postgemv<<<wblocks, 256>>>(W1, b1, N);                                // 6
    k_gemm2<<<ggrid, 256>>>(W2, N);                                         // 7 (tf32 MMA)
    k_alphas<<<wblocks, 256>>>(asrc2, adst2, N);                            // 8
    k_agg2f<<<wblocks, 256>>>(b2, W3, N);                                   // 9 (fused)
    k_agg3<<<(N + 255) / 256, 256>>>(asrc3, adst3, b3, out, N);             // 10

    (void)n_in; (void)out_size;
}

// round 17
// speedup vs baseline: 30.7482x; 1.6075x over previous
#include <cuda_runtime.h>
#include <math.h>
#include <stdint.h>

#define NMAX   50000
#define EMAX   700000     // 650000 edges + 50000 self loops
#define FDIM   256
#define HEADS  4
#define NEG_SLOPE 0.2f

// ------- scratch: device globals, ONLY ever accessed inside kernels ---------
// (NEVER pass these as kernel args: host-side shadow + ATS = silent host-mem
//  traffic and split-brain buffers — the R8-R12 root cause)
__device__ int   g_src [EMAX];
__device__ int   g_dst [EMAX];
__device__ int   g_ssrc[EMAX];
__device__ int   g_deg [NMAX];
__device__ int   g_off [NMAX + 1];
__device__ int   g_cur [NMAX];
__device__ int   g_ticket;
__device__ volatile int g_bflag[64];
__device__ int   g_bval[64];
__device__ __align__(16) float g_ws  [8 * 128];      // W1-projected alpha vectors
__device__ __align__(16) float g_S   [NMAX * 512];   // layer-1 weighted-x sums
__device__ __align__(16) float g_feat[NMAX * FDIM];  // layer-2 h (pre-attention)
__device__ __align__(16) float g_act [NMAX * FDIM];  // layer-1 activations
__device__ __align__(16) float g_alsrc[NMAX * HEADS];
__device__ __align__(16) float g_aldst[NMAX * HEADS];
__device__ float g_h3  [NMAX];

__device__ __forceinline__ float lrelu(float x) { return x > 0.f ? x : NEG_SLOPE * x; }
__device__ __forceinline__ uint32_t f2tf(float f) {
    uint32_t r;
    asm("cvt.rna.tf32.f32 %0, %1;" : "=r"(r) : "f"(f));
    return r;
}
__device__ __forceinline__ void mma_tf32(float* d, const uint32_t* a, const uint32_t* b) {
    asm volatile(
        "mma.sync.aligned.m16n8k8.row.col.f32.tf32.tf32.f32 "
        "{%0,%1,%2,%3}, {%4,%5,%6,%7}, {%8,%9}, {%0,%1,%2,%3};"
        : "+f"(d[0]), "+f"(d[1]), "+f"(d[2]), "+f"(d[3])
        : "r"(a[0]), "r"(a[1]), "r"(a[2]), "r"(a[3]), "r"(b[0]), "r"(b[1]));
}
__device__ __forceinline__ void cp16z(uint32_t s, const void* g, int sz) {
    asm volatile("cp.async.cg.shared.global [%0], [%1], 16, %2;"
                 :: "r"(s), "l"(g), "r"(sz));
}
__device__ __forceinline__ void cp_commit() { asm volatile("cp.async.commit_group;"); }
__device__ __forceinline__ void cp_wait1()  { asm volatile("cp.async.wait_group 1;"); }

// =============== 0. ws projection (one block): g_ws[v][k] ====================
__global__ void k_ws(const float* __restrict__ W1,
                     const float* __restrict__ asrc,
                     const float* __restrict__ adst) {
    int wid = threadIdx.x >> 5, lane = threadIdx.x & 31;
    int v = wid, head = v >> 1;
    const float* avec = (v & 1) ? adst : asrc;
    float a0 = __ldg(&avec[head * 64 + lane]);
    float a1 = __ldg(&avec[head * 64 + 32 + lane]);
    for (int k = 0; k < 128; k++) {
        float s = __ldg(&W1[k * 256 + head * 64 + lane]) * a0
                + __ldg(&W1[k * 256 + head * 64 + 32 + lane]) * a1;
        #pragma unroll
        for (int o = 16; o; o >>= 1) s += __shfl_xor_sync(0xffffffffu, s, o);
        if (lane == 0) g_ws[v * 128 + k] = s;
    }
}

// =============== 1. prep: edge build+hist  ||  layer-1 alphas from x =========
__global__ __launch_bounds__(256) void k_prep(const long long* __restrict__ e, int E, int N,
                                              const float* __restrict__ x, int eblocks) {
    int bid = blockIdx.x, tid = threadIdx.x;
    if (bid < eblocks) {
        if (bid == 0 && tid < 64) {                   // reset scan state per replay
            g_bflag[tid] = 0;
            if (tid == 0) g_ticket = 0;
        }
        int i = bid * 256 + tid;
        bool is64 = true;
        #pragma unroll
        for (int j = 0; j < 8; j++) {
            unsigned long long v = (unsigned long long)__ldg(&e[j * 7 + 1]);
            if (v >= (1ULL << 31)) is64 = false;
        }
        if (i < E) {
            int s, d;
            if (is64) { s = (int)e[i]; d = (int)e[E + i]; }
            else      { const int* p = (const int*)e; s = p[i]; d = p[E + i]; }
            g_src[i] = s; g_dst[i] = d;
            atomicAdd(&g_deg[d], 1);
        } else if (i < E + N) {
            int n = i - E;
            g_src[i] = n; g_dst[i] = n;
            atomicAdd(&g_deg[n], 1);
        }
        return;
    }
    int wid = tid >> 5, lane = tid & 31;
    int n = (bid - eblocks) * 8 + wid;
    if (n >= N) return;
    float4 xv = *(const float4*)&x[(size_t)n * 128 + lane * 4];
    float dot[8];
    #pragma unroll
    for (int v = 0; v < 8; v++) {
        float4 w = *(const float4*)&g_ws[v * 128 + lane * 4];
        dot[v] = xv.x * w.x + xv.y * w.y + xv.z * w.z + xv.w * w.w;
    }
    #pragma unroll
    for (int v = 0; v < 8; v++)
        #pragma unroll
        for (int o = 16; o; o >>= 1) dot[v] += __shfl_xor_sync(0xffffffffu, dot[v], o);
    if (lane == 0) {
        *(float4*)&g_alsrc[n * 4] = make_float4(dot[0], dot[2], dot[4], dot[6]);
        *(float4*)&g_aldst[n * 4] = make_float4(dot[1], dot[3], dot[5], dot[7]);
    }
}

// =============== 2. single-launch chained scan -> g_off, g_cur ===============
__global__ __launch_bounds__(1024) void k_scan(int n) {
    __shared__ int sh[1024];
    __shared__ int s_bid, s_excl;
    int tid = threadIdx.x;
    if (tid == 0) s_bid = atomicAdd(&g_ticket, 1);
    __syncthreads();
    int bid = s_bid;
    int i = bid * 1024 + tid;
    int d = (i < n) ? g_deg[i] : 0;
    sh[tid] = d;
    __syncthreads();
    #pragma unroll
    for (int o = 1; o < 1024; o <<= 1) {
        int t = (tid >= o) ? sh[tid - o] : 0;
        __syncthreads();
        sh[tid] += t;
        __syncthreads();
    }
    if (tid == 0) {
        int excl = 0;
        if (bid > 0) {
            while (g_bflag[bid - 1] != 2) { }
            __threadfence();
            excl = g_bval[bid - 1];
        }
        g_bval[bid] = excl + sh[1023];
        __threadfence();
        g_bflag[bid] = 2;
        s_excl = excl;
    }
    __syncthreads();
    int excl = s_excl;
    if (i < n) {
        int incl = sh[tid] + excl;
        g_off[i + 1] = incl;
        g_cur[i] = incl - d;
    }
    if (i == 0) g_off[0] = 0;
}

// =============== 3. scatter (+ deg reset) — PROFILED SLOT ====================
__global__ void k_scatter(int Etot, int N) {
    int i = blockIdx.x * blockDim.x + threadIdx.x;
    if (i < Etot) {
        int p = atomicAdd(&g_cur[g_dst[i]], 1);
        g_ssrc[p] = g_src[i];
    }
    if (i < N) g_deg[i] = 0;
}

// =============== 4. layer-1 aggregation over raw x ===========================
__global__ __launch_bounds__(256) void k_aggX(const float* __restrict__ x, int N) {
    int gw = (blockIdx.x * blockDim.x + threadIdx.x) >> 5;
    int lane = threadIdx.x & 31;
    if (gw >= N) return;
    int e0 = g_off[gw], e1 = g_off[gw + 1];
    float4 ald = *(const float4*)&g_aldst[gw * 4];
    float4 a0 = make_float4(0.f, 0.f, 0.f, 0.f), a1 = a0, a2 = a0, a3 = a0;
    float s0 = 0.f, s1 = 0.f, s2 = 0.f, s3 = 0.f;
    #pragma unroll 2
    for (int e = e0; e < e1; e++) {
        int sj = __ldg(&g_ssrc[e]);
        float4 as = *(const float4*)&g_alsrc[sj * 4];
        float w0 = __expf(lrelu(as.x + ald.x));
        float w1 = __expf(lrelu(as.y + ald.y));
        float w2 = __expf(lrelu(as.z + ald.z));
        float w3 = __expf(lrelu(as.w + ald.w));
        s0 += w0; s1 += w1; s2 += w2; s3 += w3;
        float4 v = __ldg((const float4*)&x[(size_t)sj * 128] + lane);
        a0.x += w0 * v.x; a0.y += w0 * v.y; a0.z += w0 * v.z; a0.w += w0 * v.w;
        a1.x += w1 * v.x; a1.y += w1 * v.y; a1.z += w1 * v.z; a1.w += w1 * v.w;
        a2.x += w2 * v.x; a2.y += w2 * v.y; a2.z += w2 * v.z; a2.w += w2 * v.w;
        a3.x += w3 * v.x; a3.y += w3 * v.y; a3.z += w3 * v.z; a3.w += w3 * v.w;
    }
    float i0 = 1.f / (s0 + 1e-16f), i1 = 1.f / (s1 + 1e-16f);
    float i2 = 1.f / (s2 + 1e-16f), i3 = 1.f / (s3 + 1e-16f);
    float4* Sp = (float4*)&g_S[(size_t)gw * 512];
    Sp[lane]      = make_float4(a0.x * i0, a0.y * i0, a0.z * i0, a0.w * i0);
    Sp[32 + lane] = make_float4(a1.x * i1, a1.y * i1, a1.z * i1, a1.w * i1);
    Sp[64 + lane] = make_float4(a2.x * i2, a2.y * i2, a2.z * i2, a2.w * i2);
    Sp[96 + lane] = make_float4(a3.x * i3, a3.y * i3, a3.z * i3, a3.w * i3);
}

// =============== 5. layer-1 post-GEMM (tf32 MMA, per-head): =================
// g_act[:, h*64:(h+1)*64] = ELU(g_S[:, h*128:(h+1)*128] @ W1[:, h*64:+64] + b1)
// BM=128 BN=64 BK=16, 256 threads, warp tile 32x32, grid.z = head
__global__ __launch_bounds__(256) void k_postgemm(const float* __restrict__ W1,
                                                  const float* __restrict__ b1, int M) {
    __shared__ float As[2][128][20];
    __shared__ float Bs[2][16][72];
    int h = blockIdx.z;
    int tid = threadIdx.x;
    int lane = tid & 31, wid = tid >> 5;
    int gid = lane >> 2, tig = lane & 3;
    int warp_m = wid >> 1, warp_n = wid & 1;
    int brow = blockIdx.y * 128;

    int ar0 = tid >> 2,          ak0 = (tid & 3) << 2;          // A: 2 chunks/thr
    int ar1 = (tid + 256) >> 2,  ak1 = ((tid + 256) & 3) << 2;
    int bk0 = tid >> 4,          bn0 = (tid & 15) << 2;         // B: 1 chunk/thr
    bool av0 = (brow + ar0) < M, av1 = (brow + ar1) < M;
    const float* Ar0 = g_S + (size_t)(av0 ? brow + ar0 : 0) * 512 + h * 128 + ak0;
    const float* Ar1 = g_S + (size_t)(av1 ? brow + ar1 : 0) * 512 + h * 128 + ak1;
    const float* Br0 = W1 + (size_t)bk0 * 256 + h * 64 + bn0;

    uint32_t sa0[2], sa1[2], sb0[2];
    #pragma unroll
    for (int s = 0; s < 2; s++) {
        sa0[s] = (uint32_t)__cvta_generic_to_shared(&As[s][ar0][ak0]);
        sa1[s] = (uint32_t)__cvta_generic_to_shared(&As[s][ar1][ak1]);
        sb0[s] = (uint32_t)__cvta_generic_to_shared(&Bs[s][bk0][bn0]);
    }

    float acc[2][4][4];
    #pragma unroll
    for (int mt = 0; mt < 2; mt++)
        #pragma unroll
        for (int nt = 0; nt < 4; nt++)
            #pragma unroll
            for (int q = 0; q < 4; q++) acc[mt][nt][q] = 0.f;

    const int ntile = 8;                       // K=128
    cp16z(sa0[0], Ar0, av0 ? 16 : 0);
    cp16z(sa1[0], Ar1, av1 ? 16 : 0);
    cp16z(sb0[0], Br0, 16);
    cp_commit();

    for (int t = 0; t < ntile; t++) {
        int nxt = t + 1;
        if (nxt < ntile) {
            int slot = nxt & 1;
            cp16z(sa0[slot], Ar0 + nxt * 16, av0 ? 16 : 0);
            cp16z(sa1[slot], Ar1 + nxt * 16, av1 ? 16 : 0);
            cp16z(sb0[slot], Br0 + (size_t)nxt * 16 * 256, 16);
        }
        cp_commit();
        cp_wait1();
        __syncthreads();
        int cur = t & 1;
        #pragma unroll
        for (int k8 = 0; k8 < 2; k8++) {
            int kb = k8 * 8;
            uint32_t af[2][4];
            #pragma unroll
            for (int mt = 0; mt < 2; mt++) {
                int mb = warp_m * 32 + mt * 16 + gid;
                af[mt][0] = f2tf(As[cur][mb    ][kb + tig]);
                af[mt][1] = f2tf(As[cur][mb + 8][kb + tig]);
                af[mt][2] = f2tf(As[cur][mb    ][kb + tig + 4]);
                af[mt][3] = f2tf(As[cur][mb + 8][kb + tig + 4]);
            }
            uint32_t bf[4][2];
            #pragma unroll
            for (int nt = 0; nt < 4; nt++) {
                int nb = warp_n * 32 + nt * 8 + gid;
                bf[nt][0] = f2tf(Bs[cur][kb + tig    ][nb]);
                bf[nt][1] = f2tf(Bs[cur][kb + tig + 4][nb]);
            }
            #pragma unroll
            for (int mt = 0; mt < 2; mt++)
                #pragma unroll
                for (int nt = 0; nt < 4; nt++)
                    mma_tf32(acc[mt][nt], af[mt], bf[nt]);
        }
        __syncthreads();
    }
    #pragma unroll
    for (int mt = 0; mt < 2; mt++) {
        int r0 = brow + warp_m * 32 + mt * 16 + gid;
        #pragma unroll
        for (int nt = 0; nt < 4; nt++) {
            int c = warp_n * 32 + nt * 8 + 2 * tig;           // within head
            float bb0 = __ldg(&b1[h * 64 + c]);
            float bb1 = __ldg(&b1[h * 64 + c + 1]);
            if (r0 < M) {
                float v0 = acc[mt][nt][0] + bb0;
                float v1 = acc[mt][nt][1] + bb1;
                v0 = v0 > 0.f ? v0 : (__expf(v0) - 1.f);
                v1 = v1 > 0.f ? v1 : (__expf(v1) - 1.f);
                *(float2*)&g_act[(size_t)r0 * FDIM + h * 64 + c] = make_float2(v0, v1);
            }
            if (r0 + 8 < M) {
                float v2 = acc[mt][nt][2] + bb0;
                float v3 = acc[mt][nt][3] + bb1;
                v2 = v2 > 0.f ? v2 : (__expf(v2) - 1.f);
                v3 = v3 > 0.f ? v3 : (__expf(v3) - 1.f);
                *(float2*)&g_act[(size_t)(r0 + 8) * FDIM + h * 64 + c] = make_float2(v2, v3);
            }
        }
    }
}

// =============== 6. layer-2 GEMM (tf32 MMA) + fused layer-2 alphas ===========
// g_feat = g_act @ W2; each warp's 64-col section == one head, so the per-row
// attention dots are computed exactly in the epilogue (no atomics).
__global__ __launch_bounds__(256) void k_gemm2(const float* __restrict__ B,
                                               const float* __restrict__ asrc2,
                                               const float* __restrict__ adst2, int M) {
    __shared__ float As[2][128][20];
    __shared__ float Bs[2][16][136];
    const float* A = g_act;
    int tid = threadIdx.x;
    int lane = tid & 31, wid = tid >> 5;
    int gid = lane >> 2, tig = lane & 3;
    int warp_m = wid >> 1, warp_n = wid & 1;
    int brow = blockIdx.y * 128, bcol = blockIdx.x * 128;
    int hh = blockIdx.x * 2 + warp_n;          // head owned by this warp

    int ar0 = tid >> 2,          ak0 = (tid & 3) << 2;
    int ar1 = (tid + 256) >> 2,  ak1 = ((tid + 256) & 3) << 2;
    int bk0 = tid >> 5,          bn0 = (tid & 31) << 2;
    int bk1 = (tid + 256) >> 5,  bn1 = ((tid + 256) & 31) << 2;
    bool av0 = (brow + ar0) < M, av1 = (brow + ar1) < M;
    const float* Ar0 = A + (size_t)(av0 ? brow + ar0 : 0) * FDIM + ak0;
    const float* Ar1 = A + (size_t)(av1 ? brow + ar1 : 0) * FDIM + ak1;
    const float* Br0 = B + (size_t)bk0 * FDIM + bcol + bn0;
    const float* Br1 = B + (size_t)bk1 * FDIM + bcol + bn1;

    uint32_t sa0[2], sa1[2], sb0[2], sb1[2];
    #pragma unroll
    for (int s = 0; s < 2; s++) {
        sa0[s] = (uint32_t)__cvta_generic_to_shared(&As[s][ar0][ak0]);
        sa1[s] = (uint32_t)__cvta_generic_to_shared(&As[s][ar1][ak1]);
        sb0[s] = (uint32_t)__cvta_generic_to_shared(&Bs[s][bk0][bn0]);
        sb1[s] = (uint32_t)__cvta_generic_to_shared(&Bs[s][bk1][bn1]);
    }

    float acc[2][8][4];
    #pragma unroll
    for (int mt = 0; mt < 2; mt++)
        #pragma unroll
        for (int nt = 0; nt < 8; nt++)
            #pragma unroll
            for (int q = 0; q < 4; q++) acc[mt][nt][q] = 0.f;

    const int ntile = FDIM >> 4;
    cp16z(sa0[0], Ar0, av0 ? 16 : 0);
    cp16z(sa1[0], Ar1, av1 ? 16 : 0);
    cp16z(sb0[0], Br0, 16);
    cp16z(sb1[0], Br1, 16);
    cp_commit();

    for (int t = 0; t < ntile; t++) {
        int nxt = t + 1;
        if (nxt < ntile) {
            int slot = nxt & 1;
            cp16z(sa0[slot], Ar0 + nxt * 16, av0 ? 16 : 0);
            cp16z(sa1[slot], Ar1 + nxt * 16, av1 ? 16 : 0);
            cp16z(sb0[slot], Br0 + (size_t)nxt * 16 * FDIM, 16);
            cp16z(sb1[slot], Br1 + (size_t)nxt * 16 * FDIM, 16);
        }
        cp_commit();
        cp_wait1();
        __syncthreads();
        int cur = t & 1;
        #pragma unroll
        for (int k8 = 0; k8 < 2; k8++) {
            int kb = k8 * 8;
            uint32_t af[2][4];
            #pragma unroll
            for (int mt = 0; mt < 2; mt++) {
                int mb = warp_m * 32 + mt * 16 + gid;
                af[mt][0] = f2tf(As[cur][mb    ][kb + tig]);
                af[mt][1] = f2tf(As[cur][mb + 8][kb + tig]);
                af[mt][2] = f2tf(As[cur][mb    ][kb + tig + 4]);
                af[mt][3] = f2tf(As[cur][mb + 8][kb + tig + 4]);
            }
            uint32_t bf[8][2];
            #pragma unroll
            for (int nt = 0; nt < 8; nt++) {
                int nb = warp_n * 64 + nt * 8 + gid;
                bf[nt][0] = f2tf(Bs[cur][kb + tig    ][nb]);
                bf[nt][1] = f2tf(Bs[cur][kb + tig + 4][nb]);
            }
            #pragma unroll
            for (int mt = 0; mt < 2; mt++)
                #pragma unroll
                for (int nt = 0; nt < 8; nt++)
                    mma_tf32(acc[mt][nt], af[mt], bf[nt]);
        }
        __syncthreads();
    }
    // epilogue: write feat + compute per-row alpha dots for head hh
    #pragma unroll
    for (int mt = 0; mt < 2; mt++) {
        int r0 = brow + warp_m * 32 + mt * 16 + gid;
        float pS0 = 0.f, pD0 = 0.f, pS8 = 0.f, pD8 = 0.f;
        #pragma unroll
        for (int nt = 0; nt < 8; nt++) {
            int c = bcol + warp_n * 64 + nt * 8 + 2 * tig;
            int cl = hh * 64 + (nt * 8 + 2 * tig);            // == c
            float a0 = __ldg(&asrc2[cl]),     a1 = __ldg(&asrc2[cl + 1]);
            float d0 = __ldg(&adst2[cl]),     d1 = __ldg(&adst2[cl + 1]);
            pS0 += acc[mt][nt][0] * a0 + acc[mt][nt][1] * a1;
            pD0 += acc[mt][nt][0] * d0 + acc[mt][nt][1] * d1;
            pS8 += acc[mt][nt][2] * a0 + acc[mt][nt][3] * a1;
            pD8 += acc[mt][nt][2] * d0 + acc[mt][nt][3] * d1;
            if (r0 < M)
                *(float2*)&g_feat[(size_t)r0 * FDIM + c] = make_float2(acc[mt][nt][0], acc[mt][nt][1]);
            if (r0 + 8 < M)
                *(float2*)&g_feat[(size_t)(r0 + 8) * FDIM + c] = make_float2(acc[mt][nt][2], acc[mt][nt][3]);
        }
        #pragma unroll
        for (int mk = 1; mk <= 2; mk <<= 1) {                 // reduce over tig group
            pS0 += __shfl_xor_sync(0xffffffffu, pS0, mk);
            pD0 += __shfl_xor_sync(0xffffffffu, pD0, mk);
            pS8 += __shfl_xor_sync(0xffffffffu, pS8, mk);
            pD8 += __shfl_xor_sync(0xffffffffu, pD8, mk);
        }
        if (tig == 0) {
            if (r0 < M)     { g_alsrc[r0 * 4 + hh] = pS0;       g_aldst[r0 * 4 + hh] = pD0; }
            if (r0 + 8 < M) { g_alsrc[(r0 + 8) * 4 + hh] = pS8; g_aldst[(r0 + 8) * 4 + hh] = pD8; }
        }
    }
}

// =============== 7. layer-2 aggregation + bias + ELU + W3-dot (fused) ========
__global__ __launch_bounds__(256) void k_agg2f(const float* __restrict__ bias,
                                               const float* __restrict__ W3, int N) {
    int gw = (blockIdx.x * blockDim.x + threadIdx.x) >> 5;
    int lane = threadIdx.x & 31;
    if (gw >= N) return;
    int e0 = g_off[gw], e1 = g_off[gw + 1];
    float4 ald = *(const float4*)&g_aldst[gw * 4];
    bool lo = lane < 16;
    float4 accA = make_float4(0.f, 0.f, 0.f, 0.f);
    float4 accB = make_float4(0.f, 0.f, 0.f, 0.f);
    float s0 = 0.f, s1 = 0.f, s2 = 0.f, s3 = 0.f;
    #pragma unroll 2
    for (int e = e0; e < e1; e++) {
        int sj = __ldg(&g_ssrc[e]);
        float4 as = *(const float4*)&g_alsrc[sj * 4];
        float w0 = __expf(lrelu(as.x + ald.x));
        float w1 = __expf(lrelu(as.y + ald.y));
        float w2 = __expf(lrelu(as.z + ald.z));
        float w3 = __expf(lrelu(as.w + ald.w));
        s0 += w0; s1 += w1; s2 += w2; s3 += w3;
        const float4* hp = (const float4*)&g_feat[(size_t)sj * FDIM];
        float4 vA = __ldg(hp + lane);
        float4 vB = __ldg(hp + 32 + lane);
        float wA = lo ? w0 : w1;
        float wB = lo ? w2 : w3;
        accA.x += wA * vA.x; accA.y += wA * vA.y; accA.z += wA * vA.z; accA.w += wA * vA.w;
        accB.x += wB * vB.x; accB.y += wB * vB.y; accB.z += wB * vB.z; accB.w += wB * vB.w;
    }
    float invA = 1.f / ((lo ? s0 : s1) + 1e-16f);
    float invB = 1.f / ((lo ? s2 : s3) + 1e-16f);
    float4 bA = __ldg((const float4*)bias + lane);
    float4 bB = __ldg((const float4*)bias + 32 + lane);
    float4 oA, oB;
    oA.x = accA.x * invA + bA.x; oA.y = accA.y * invA + bA.y;
    oA.z = accA.z * invA + bA.z; oA.w = accA.w * invA + bA.w;
    oB.x = accB.x * invB + bB.x; oB.y = accB.y * invB + bB.y;
    oB.z = accB.z * invB + bB.z; oB.w = accB.w * invB + bB.w;
    oA.x = oA.x > 0.f ? oA.x : (__expf(oA.x) - 1.f);
    oA.y = oA.y > 0.f ? oA.y : (__expf(oA.y) - 1.f);
    oA.z = oA.z > 0.f ? oA.z : (__expf(oA.z) - 1.f);
    oA.w = oA.w > 0.f ? oA.w : (__expf(oA.w) - 1.f);
    oB.x = oB.x > 0.f ? oB.x : (__expf(oB.x) - 1.f);
    oB.y = oB.y > 0.f ? oB.y : (__expf(oB.y) - 1.f);
    oB.z = oB.z > 0.f ? oB.z : (__expf(oB.z) - 1.f);
    oB.w = oB.w > 0.f ? oB.w : (__expf(oB.w) - 1.f);
    float4 wA4 = __ldg((const float4*)W3 + lane);
    float4 wB4 = __ldg((const float4*)W3 + 32 + lane);
    float p = oA.x * wA4.x + oA.y * wA4.y + oA.z * wA4.z + oA.w * wA4.w
            + oB.x * wB4.x + oB.y * wB4.y + oB.z * wB4.z + oB.w * wB4.w;
    #pragma unroll
    for (int o = 16; o; o >>= 1) p += __shfl_xor_sync(0xffffffffu, p, o);
    if (lane == 0) g_h3[gw] = p;
}

// =============== 8. layer-3 aggregation -> d_out =============================
__global__ void k_agg3(const float* __restrict__ asrc3, const float* __restrict__ adst3,
                       const float* __restrict__ b3, float* __restrict__ out, int N) {
    int n = blockIdx.x * blockDim.x + threadIdx.x;
    if (n >= N) return;
    float as = __ldg(&asrc3[0]);
    float hd = g_h3[n] * __ldg(&adst3[0]);
    int e0 = g_off[n], e1 = g_off[n + 1];
    float num = 0.f, den = 0.f;
    #pragma unroll 4
    for (int e = e0; e < e1; e++) {
        float hs = g_h3[__ldg(&g_ssrc[e])];
        float w = __expf(lrelu(hs * as + hd));
        num += w * hs;
        den += w;
    }
    out[n] = num / (den + 1e-16f) + __ldg(&b3[0]);
}

// ---------------- launch: ONLY harness pointers cross the boundary ----------
extern "C" void kernel_launch(void* const* d_in, const int* in_sizes, int n_in,
                              void* d_out, int out_size) {
    const float* x      = (const float*)d_in[0];
    const void*  eidx   = d_in[1];
    const float* W1     = (const float*)d_in[2];
    const float* asrc1  = (const float*)d_in[3];
    const float* adst1  = (const float*)d_in[4];
    const float* b1     = (const float*)d_in[5];
    const float* W2     = (const float*)d_in[6];
    const float* asrc2  = (const float*)d_in[7];
    const float* adst2  = (const float*)d_in[8];
    const float* b2     = (const float*)d_in[9];
    const float* W3     = (const float*)d_in[10];
    const float* asrc3  = (const float*)d_in[11];
    const float* adst3  = (const float*)d_in[12];
    const float* b3     = (const float*)d_in[13];
    float* out = (float*)d_out;

    int N = in_sizes[0] / 128;        // 50000
    int E = in_sizes[1] / 2;          // 650000
    int Etot = E + N;
    int nb = (N + 1023) / 1024;

    int eblocks = (Etot + 255) / 256;
    int ablocks = (N + 7) / 8;
    int wblocks = (N + 7) / 8;
    dim3 ggrid(FDIM / 128, (N + 127) / 128);
    dim3 pgrid(1, (N + 127) / 128, HEADS);

    k_ws<<<1, 256>>>(W1, asrc1, adst1);                                     // 1
    k_prep<<<eblocks + ablocks, 256>>>((const long long*)eidx, E, N, x,
                                       eblocks);                            // 2
    k_scan<<<nb, 1024>>>(N);                                                // 3
    k_scatter<<<eblocks, 256>>>(Etot, N);                                   // 4 (profiled)
    k_aggX<<<wblocks, 256>>>(x, N);                                         // 5
    k_postgemm<<<pgrid, 256>>>(W1, b1, N);                                  // 6 (tf32 MMA)
    k_gemm2<<<ggrid, 256>>>(W2, asrc2, adst2, N);                           // 7 (tf32 + fused alphas)
    k_agg2f<<<wblocks, 256>>>(b2, W3, N);                                   // 8 (fused)
    k_agg3<<<(N + 255) / 256, 256>>>(asrc3, adst3, b3, out, N);             // 9

    (void)n_in; (void)out_size;
}